// round 3
// baseline (speedup 1.0000x reference)
#include <cuda_runtime.h>
#include <cstdint>

// Problem constants (fixed by dataset):
// b=2, s=256, C=128, H=W=16, YH=XH=CH=2 -> nH=8 heads, c=64, h=w=8, D=4096
// mask: 16x16 token grid, radius-1 neighborhood (<=9 keys per query)

#define NTOK   512
#define FDIM   4096
#define SLICE  (256*4096)

// Scratch (device globals -- allocation-free per harness rules)
__device__ float g_q[2*8*256*4096];
__device__ float g_k[2*8*256*4096];
__device__ float g_v[2*8*256*4096];
__device__ __align__(16) uint32_t g_sa[512*256*128];   // tf32 bits, [t][p=H*W][C]
__device__ __align__(16) uint32_t g_xt[512*256*128];   // tf32 bits, [t][p][k=C]
__device__ __align__(16) uint32_t g_wt[3*128*128];     // tf32 w_qkv
__device__ __align__(16) uint32_t g_wto[128*128];      // tf32 w_out

// ---------------------------------------------------------------------------
// helpers
// ---------------------------------------------------------------------------
__device__ __forceinline__ uint32_t f2tf32(float x) {
    uint32_t r;
    asm("cvt.rna.tf32.f32 %0, %1;" : "=r"(r) : "f"(x));
    return r;
}

__device__ __forceinline__ void mma_tf32(float* c,
                                         uint32_t a0, uint32_t a1, uint32_t a2, uint32_t a3,
                                         uint32_t b0, uint32_t b1) {
    asm volatile(
        "mma.sync.aligned.m16n8k8.row.col.f32.tf32.tf32.f32 "
        "{%0,%1,%2,%3}, {%4,%5,%6,%7}, {%8,%9}, {%0,%1,%2,%3};"
        : "+f"(c[0]), "+f"(c[1]), "+f"(c[2]), "+f"(c[3])
        : "r"(a0), "r"(a1), "r"(a2), "r"(a3), "r"(b0), "r"(b1));
}

__device__ __forceinline__ void cp16(uint32_t* smem_dst, const uint32_t* gsrc) {
    uint32_t s = (uint32_t)__cvta_generic_to_shared(smem_dst);
    asm volatile("cp.async.ca.shared.global [%0], [%1], 16;" :: "r"(s), "l"(gsrc));
}

// ---------------------------------------------------------------------------
// Pre-conversion kernels
// ---------------------------------------------------------------------------
__global__ __launch_bounds__(256) void prep_w(const float* __restrict__ wq,
                                              const float* __restrict__ wo) {
    int i = blockIdx.x * 256 + threadIdx.x;   // grid 192 -> 49152 threads
    g_wt[i] = f2tf32(wq[i]);
    if (i < 16384) g_wto[i] = f2tf32(wo[i]);
}

// transpose seq[t][c][p] -> g_xt[t][p][c], tf32-rounded. one block per token.
__global__ __launch_bounds__(256) void prep_x(const float* __restrict__ seq) {
    const int t = blockIdx.x;
    __shared__ float tile[32][33];
    const float* src = seq + (size_t)t * 32768;
    uint32_t* dst = g_xt + (size_t)t * 32768;

    for (int cc = 0; cc < 4; cc++)
        for (int pc = 0; pc < 8; pc++) {
            #pragma unroll
            for (int j = 0; j < 4; j++) {
                int id = threadIdx.x + j * 256;
                int r = id >> 5, cl = id & 31;
                tile[r][cl] = src[(cc * 32 + r) * 256 + pc * 32 + cl];
            }
            __syncthreads();
            #pragma unroll
            for (int j = 0; j < 4; j++) {
                int id = threadIdx.x + j * 256;
                int r = id >> 5, cl = id & 31;
                dst[(size_t)(pc * 32 + r) * 128 + cc * 32 + cl] = f2tf32(tile[cl][r]);
            }
            __syncthreads();
        }
}

// ---------------------------------------------------------------------------
// Pipelined tf32 GEMM core: C[128,128] = W[128,128] * X^T (X stored [p][k])
// 8 warps (4x2), warp tile 32x64 = 2x8 m16n8k8. K-tile 32, 2-stage cp.async.
// smem (dynamic): As[2][128][36], Bs[2][128][36] u32 = 73728 B
// ---------------------------------------------------------------------------
struct GemmCtx { int lane, wm, wn; };

__device__ __forceinline__ void gemm128_pipe(
    const uint32_t* __restrict__ wmat,   // [128][128] tf32, k contiguous
    const uint32_t* __restrict__ xmat,   // [128 p][128 k] tf32, k contiguous
    uint32_t* smem, float acc[2][8][4], GemmCtx& cx)
{
    const int tid = threadIdx.x;
    const int lane = tid & 31, wid = tid >> 5;
    cx.lane = lane; cx.wm = wid >> 1; cx.wn = wid & 1;

    #pragma unroll
    for (int mf = 0; mf < 2; mf++)
        #pragma unroll
        for (int nf = 0; nf < 8; nf++)
            #pragma unroll
            for (int r = 0; r < 4; r++) acc[mf][nf][r] = 0.f;

    auto issue = [&](int buf, int kk) {
        uint32_t* Ab = smem + buf * 4608;
        uint32_t* Bb = smem + 9216 + buf * 4608;
        #pragma unroll
        for (int i = 0; i < 4; i++) {
            int id  = tid + i * 256;            // 0..1023
            int row = id >> 3, off = id & 7;
            cp16(Ab + row * 36 + off * 4, wmat + row * 128 + kk + off * 4);
            cp16(Bb + row * 36 + off * 4, xmat + row * 128 + kk + off * 4);
        }
        asm volatile("cp.async.commit_group;" ::: "memory");
    };

    issue(0, 0);

    #pragma unroll
    for (int kt = 0; kt < 4; kt++) {
        if (kt < 3) {
            issue((kt + 1) & 1, (kt + 1) * 32);
            asm volatile("cp.async.wait_group 1;" ::: "memory");
        } else {
            asm volatile("cp.async.wait_group 0;" ::: "memory");
        }
        __syncthreads();

        const uint32_t (*As)[36] = (const uint32_t (*)[36])(smem + (kt & 1) * 4608);
        const uint32_t (*Bs)[36] = (const uint32_t (*)[36])(smem + 9216 + (kt & 1) * 4608);

        #pragma unroll
        for (int ks = 0; ks < 32; ks += 8) {
            const int kq = lane & 3;
            uint32_t bf[8][2];
            #pragma unroll
            for (int nf = 0; nf < 8; nf++) {
                int n = cx.wn * 64 + nf * 8 + (lane >> 2);
                bf[nf][0] = Bs[n][ks + kq];
                bf[nf][1] = Bs[n][ks + kq + 4];
            }
            #pragma unroll
            for (int mf = 0; mf < 2; mf++) {
                int m = cx.wm * 32 + mf * 16 + (lane >> 2);
                uint32_t a0 = As[m    ][ks + kq];
                uint32_t a1 = As[m + 8][ks + kq];
                uint32_t a2 = As[m    ][ks + kq + 4];
                uint32_t a3 = As[m + 8][ks + kq + 4];
                #pragma unroll
                for (int nf = 0; nf < 8; nf++)
                    mma_tf32(acc[mf][nf], a0, a1, a2, a3, bf[nf][0], bf[nf][1]);
            }
        }
        __syncthreads();
    }
}

// ---------------------------------------------------------------------------
// Kernel A: QKV projection -> scatter into per-head layout g_{q,k,v}[b][n][s][f]
// grid: (token 512, dtile 3, ptile 2), block 256, dyn smem 73728
// ---------------------------------------------------------------------------
__global__ __launch_bounds__(256) void qkv_gemm() {
    const int t  = blockIdx.x;
    const int dt = blockIdx.y;
    const int pt = blockIdx.z;

    extern __shared__ uint32_t smem[];
    float acc[2][8][4];
    GemmCtx cx;
    gemm128_pipe(g_wt + dt * 16384,
                 g_xt + (size_t)t * 32768 + pt * 16384,
                 smem, acc, cx);

    const int b_ = t >> 8, s_ = t & 255;
    float* dst = (dt == 0) ? g_q : (dt == 1) ? g_k : g_v;

    #pragma unroll
    for (int mf = 0; mf < 2; mf++) {
        #pragma unroll
        for (int half = 0; half < 2; half++) {
            const int dl = cx.wm * 32 + mf * 16 + (cx.lane >> 2) + half * 8;
            const int ch = dl >> 6, cidx = dl & 63;
            #pragma unroll
            for (int nf = 0; nf < 8; nf++) {
                const int c0 = cx.wn * 64 + nf * 8 + 2 * (cx.lane & 3);
                const int p0 = pt * 128 + c0;
                const int Hi = p0 >> 4, Wi = p0 & 15;
                const int ys = Hi >> 3, hy = Hi & 7, xs = Wi >> 3, wx = Wi & 7;
                const int n = (ys * 2 + xs) * 2 + ch;
                const size_t base = ((size_t)((b_ * 8 + n) * 256 + s_)) * FDIM
                                  + cidx * 64 + hy * 8 + wx;
                float2 v = make_float2(acc[mf][nf][half * 2], acc[mf][nf][half * 2 + 1]);
                *reinterpret_cast<float2*>(dst + base) = v;
            }
        }
    }
}

// ---------------------------------------------------------------------------
// Kernel B: masked attention (fp32). One block (256 thr) per (b, head, query).
// Epilogue: write sa transposed [t][p][C], tf32 bits, via smem staging.
// ---------------------------------------------------------------------------
__global__ __launch_bounds__(256) void attn_kernel() {
    const int idx = blockIdx.x;
    const int i   = idx & 255;
    const int n   = (idx >> 8) & 7;
    const int b_  = idx >> 11;
    const int tid = threadIdx.x;

    const size_t slice = (size_t)(b_ * 8 + n) * SLICE;
    const size_t qb    = slice + (size_t)i * FDIM;

    float qreg[16];
    #pragma unroll
    for (int t = 0; t < 16; t++) qreg[t] = g_q[qb + t * 256 + tid];

    const int iy = i >> 4, ix = i & 15;
    int jidx[9]; int nj = 0;
    for (int dy = -1; dy <= 1; dy++) {
        int jy = iy + dy; if (jy < 0 || jy > 15) continue;
        for (int dx = -1; dx <= 1; dx++) {
            int jx = ix + dx; if (jx < 0 || jx > 15) continue;
            jidx[nj++] = jy * 16 + jx;
        }
    }

    float part[9];
    for (int jj = 0; jj < nj; jj++) {
        const float* kb = g_k + slice + (size_t)jidx[jj] * FDIM;
        float p = 0.f;
        #pragma unroll
        for (int t = 0; t < 16; t++) p += qreg[t] * kb[t * 256 + tid];
        part[jj] = p;
    }

    __shared__ float red[9][8];
    __shared__ float sm[9];
    for (int jj = 0; jj < nj; jj++) {
        float v = part[jj];
        #pragma unroll
        for (int o = 16; o > 0; o >>= 1) v += __shfl_down_sync(0xffffffffu, v, o);
        if ((tid & 31) == 0) red[jj][tid >> 5] = v;
    }
    __syncthreads();
    if (tid < nj) {
        float s = 0.f;
        #pragma unroll
        for (int w = 0; w < 8; w++) s += red[tid][w];
        sm[tid] = s * 0.015625f;
    }
    __syncthreads();

    float sc[9];
    float m = -1e30f;
    for (int jj = 0; jj < nj; jj++) { sc[jj] = sm[jj]; m = fmaxf(m, sc[jj]); }
    float sum = 0.f;
    for (int jj = 0; jj < nj; jj++) { sc[jj] = __expf(sc[jj] - m); sum += sc[jj]; }
    const float inv = 1.0f / sum;

    float facc[16];
    #pragma unroll
    for (int t = 0; t < 16; t++) facc[t] = 0.f;
    for (int jj = 0; jj < nj; jj++) {
        const float a = sc[jj] * inv;
        const float* vb = g_v + slice + (size_t)jidx[jj] * FDIM;
        #pragma unroll
        for (int t = 0; t < 16; t++) facc[t] += a * vb[t * 256 + tid];
    }

    // Stage into smem: ssa[r=hy*8+wx][cidx], then coalesced transposed store.
    __shared__ float ssa[64][65];
    #pragma unroll
    for (int t = 0; t < 16; t++) {
        int f = t * 256 + tid;            // f = cidx*64 + r
        ssa[f & 63][f >> 6] = facc[t];
    }
    __syncthreads();

    const int ch = n & 1, sp = n >> 1, ys = sp >> 1, xs = sp & 1;
    uint32_t* dstT = g_sa + (size_t)(b_ * 256 + i) * 32768;
    const int r  = tid >> 2;              // 0..63 local spatial index
    const int cb = (tid & 3) * 16;        // 16-col chunk
    const int HWp = (ys * 8 + (r >> 3)) * 16 + xs * 8 + (r & 7);
    uint32_t* row = dstT + (size_t)HWp * 128 + ch * 64 + cb;
    #pragma unroll
    for (int j = 0; j < 16; j += 4) {
        uint4 v;
        v.x = f2tf32(ssa[r][cb + j    ]);
        v.y = f2tf32(ssa[r][cb + j + 1]);
        v.z = f2tf32(ssa[r][cb + j + 2]);
        v.w = f2tf32(ssa[r][cb + j + 3]);
        *reinterpret_cast<uint4*>(row + j) = v;
    }
}

// ---------------------------------------------------------------------------
// Kernel C: output projection + bias. grid: (token 512, ptile 2), block 256
// ---------------------------------------------------------------------------
__global__ __launch_bounds__(256) void out_gemm(const float* __restrict__ b_out,
                                                float* __restrict__ out) {
    const int t  = blockIdx.x;
    const int pt = blockIdx.y;

    extern __shared__ uint32_t smem[];
    float acc[2][8][4];
    GemmCtx cx;
    gemm128_pipe(g_wto,
                 g_sa + (size_t)t * 32768 + pt * 16384,
                 smem, acc, cx);

    #pragma unroll
    for (int mf = 0; mf < 2; mf++) {
        #pragma unroll
        for (int half = 0; half < 2; half++) {
            const int d = cx.wm * 32 + mf * 16 + (cx.lane >> 2) + half * 8;
            const float bias = b_out[d];
            #pragma unroll
            for (int nf = 0; nf < 8; nf++) {
                const int c0 = cx.wn * 64 + nf * 8 + 2 * (cx.lane & 3);
                float2 v = make_float2(acc[mf][nf][half * 2] + bias,
                                       acc[mf][nf][half * 2 + 1] + bias);
                *reinterpret_cast<float2*>(out + (size_t)t * 32768
                                           + (size_t)d * 256 + pt * 128 + c0) = v;
            }
        }
    }
}

extern "C" void kernel_launch(void* const* d_in, const int* in_sizes, int n_in,
                              void* d_out, int out_size) {
    const float* seq   = (const float*)d_in[0];
    const float* w_qkv = (const float*)d_in[1];
    const float* w_out = (const float*)d_in[2];
    const float* b_out = (const float*)d_in[3];
    float* out = (float*)d_out;

    const int dynsmem = 73728;
    cudaFuncSetAttribute(qkv_gemm, cudaFuncAttributeMaxDynamicSharedMemorySize, dynsmem);
    cudaFuncSetAttribute(out_gemm, cudaFuncAttributeMaxDynamicSharedMemorySize, dynsmem);

    prep_w<<<192, 256>>>(w_qkv, w_out);
    prep_x<<<512, 256>>>(seq);

    dim3 gA(NTOK, 3, 2);
    qkv_gemm<<<gA, 256, dynsmem>>>();

    attn_kernel<<<4096, 256>>>();

    dim3 gC(NTOK, 2);
    out_gemm<<<gC, 256, dynsmem>>>(b_out, out);
}

// round 5
// speedup vs baseline: 1.1183x; 1.1183x over previous
#include <cuda_runtime.h>
#include <cstdint>

// Problem constants (fixed by dataset):
// b=2, s=256, C=128, H=W=16, YH=XH=CH=2 -> nH=8 heads, c=64, h=w=8, D=4096
// mask: 16x16 token grid, radius-1 neighborhood (<=9 keys per query)

#define NTOK   512
#define FDIM   4096
#define SLICE  (256*4096)

// Scratch (device globals -- allocation-free per harness rules)
__device__ float g_q[2*8*256*4096];
__device__ float g_k[2*8*256*4096];
__device__ float g_v[2*8*256*4096];
__device__ __align__(16) uint32_t g_sa[512*256*128];   // tf32 bits, [t][p][C], k-permuted
__device__ __align__(16) uint32_t g_xt[512*256*128];   // tf32 bits, [t][p][k], k-permuted
__device__ __align__(16) uint32_t g_wt[3*128*128];     // tf32 w_qkv, k-permuted
__device__ __align__(16) uint32_t g_wto[128*128];      // tf32 w_out, k-permuted

// k-permutation within each aligned 32-k tile: kperm = (k&3)*8 + (k>>2)
__device__ __forceinline__ int kperm32(int kl) { return ((kl & 3) << 3) | (kl >> 2); }

// ---------------------------------------------------------------------------
// helpers
// ---------------------------------------------------------------------------
__device__ __forceinline__ uint32_t f2tf32(float x) {
    uint32_t r;
    asm("cvt.rna.tf32.f32 %0, %1;" : "=r"(r) : "f"(x));
    return r;
}

__device__ __forceinline__ void mma_tf32(float* c,
                                         uint32_t a0, uint32_t a1, uint32_t a2, uint32_t a3,
                                         uint32_t b0, uint32_t b1) {
    asm volatile(
        "mma.sync.aligned.m16n8k8.row.col.f32.tf32.tf32.f32 "
        "{%0,%1,%2,%3}, {%4,%5,%6,%7}, {%8,%9}, {%0,%1,%2,%3};"
        : "+f"(c[0]), "+f"(c[1]), "+f"(c[2]), "+f"(c[3])
        : "r"(a0), "r"(a1), "r"(a2), "r"(a3), "r"(b0), "r"(b1));
}

__device__ __forceinline__ void cp16(uint32_t* smem_dst, const uint32_t* gsrc) {
    uint32_t s = (uint32_t)__cvta_generic_to_shared(smem_dst);
    asm volatile("cp.async.ca.shared.global [%0], [%1], 16;" :: "r"(s), "l"(gsrc));
}

// ---------------------------------------------------------------------------
// Pre-conversion kernels (write k-permuted tf32)
// ---------------------------------------------------------------------------
__global__ __launch_bounds__(256) void prep_w(const float* __restrict__ wq,
                                              const float* __restrict__ wo) {
    int i = blockIdx.x * 256 + threadIdx.x;   // grid 192
    int d = i >> 7, k = i & 127;
    int kp = (k & ~31) | kperm32(k & 31);
    g_wt[d * 128 + kp] = f2tf32(wq[i]);
    if (i < 16384) g_wto[d * 128 + kp] = f2tf32(wo[i]);
}

// transpose seq[t][c][p] -> g_xt[t][p][cperm], tf32. one block per token.
__global__ __launch_bounds__(256) void prep_x(const float* __restrict__ seq) {
    const int t = blockIdx.x;
    __shared__ float tile[32][33];
    const float* src = seq + (size_t)t * 32768;
    uint32_t* dst = g_xt + (size_t)t * 32768;

    for (int cc = 0; cc < 4; cc++)
        for (int pc = 0; pc < 8; pc++) {
            #pragma unroll
            for (int j = 0; j < 4; j++) {
                int id = threadIdx.x + j * 256;
                int r = id >> 5, cl = id & 31;
                tile[r][cl] = src[(cc * 32 + r) * 256 + pc * 32 + cl];
            }
            __syncthreads();
            #pragma unroll
            for (int j = 0; j < 4; j++) {
                int id = threadIdx.x + j * 256;
                int r = id >> 5, cl = id & 31;
                dst[(size_t)(pc * 32 + r) * 128 + cc * 32 + kperm32(cl)] = f2tf32(tile[cl][r]);
            }
            __syncthreads();
        }
}

// ---------------------------------------------------------------------------
// Pipelined tf32 GEMM core, k-permuted operands -> LDS.64 fragment loads.
// 8 warps (4x2), warp tile 32x64. K-tile 32, 2-stage cp.async.
// smem: As[2][128][36], Bs[2][128][36] u32 = 73728 B
// ---------------------------------------------------------------------------
struct GemmCtx { int lane, wm, wn; };

__device__ __forceinline__ void gemm128_pipe(
    const uint32_t* __restrict__ wmat,   // [128][128] tf32, k-permuted per 32
    const uint32_t* __restrict__ xmat,   // [128 p][128 k] tf32, k-permuted per 32
    uint32_t* smem, float acc[2][8][4], GemmCtx& cx)
{
    const int tid = threadIdx.x;
    const int lane = tid & 31, wid = tid >> 5;
    cx.lane = lane; cx.wm = wid >> 1; cx.wn = wid & 1;
    const int kq = lane & 3;
    const int rg = lane >> 2;

    #pragma unroll
    for (int mf = 0; mf < 2; mf++)
        #pragma unroll
        for (int nf = 0; nf < 8; nf++)
            #pragma unroll
            for (int r = 0; r < 4; r++) acc[mf][nf][r] = 0.f;

    auto issue = [&](int buf, int kk) {
        uint32_t* Ab = smem + buf * 4608;
        uint32_t* Bb = smem + 9216 + buf * 4608;
        #pragma unroll
        for (int i = 0; i < 4; i++) {
            int id  = tid + i * 256;            // 0..1023
            int row = id >> 3, off = id & 7;
            cp16(Ab + row * 36 + off * 4, wmat + row * 128 + kk + off * 4);
            cp16(Bb + row * 36 + off * 4, xmat + row * 128 + kk + off * 4);
        }
        asm volatile("cp.async.commit_group;" ::: "memory");
    };

    issue(0, 0);

    #pragma unroll
    for (int kt = 0; kt < 4; kt++) {
        if (kt < 3) {
            issue((kt + 1) & 1, (kt + 1) * 32);
            asm volatile("cp.async.wait_group 1;" ::: "memory");
        } else {
            asm volatile("cp.async.wait_group 0;" ::: "memory");
        }
        __syncthreads();

        const uint32_t (*As)[36] = (const uint32_t (*)[36])(smem + (kt & 1) * 4608);
        const uint32_t (*Bs)[36] = (const uint32_t (*)[36])(smem + 9216 + (kt & 1) * 4608);

        #pragma unroll
        for (int s = 0; s < 4; s++) {
            const int koff = kq * 8 + 2 * s;       // permuted: word pair = (k, k+4)
            uint2 bv[8];
            #pragma unroll
            for (int nf = 0; nf < 8; nf++) {
                int n = cx.wn * 64 + nf * 8 + rg;
                bv[nf] = *reinterpret_cast<const uint2*>(&Bs[n][koff]);
            }
            #pragma unroll
            for (int mf = 0; mf < 2; mf++) {
                int m = cx.wm * 32 + mf * 16 + rg;
                uint2 alo = *reinterpret_cast<const uint2*>(&As[m][koff]);
                uint2 ahi = *reinterpret_cast<const uint2*>(&As[m + 8][koff]);
                #pragma unroll
                for (int nf = 0; nf < 8; nf++)
                    mma_tf32(acc[mf][nf], alo.x, ahi.x, alo.y, ahi.y, bv[nf].x, bv[nf].y);
            }
        }
        __syncthreads();
    }
}

// ---------------------------------------------------------------------------
// Kernel A: QKV projection -> scatter into per-head layout g_{q,k,v}[b][n][s][f]
// ---------------------------------------------------------------------------
__global__ __launch_bounds__(256) void qkv_gemm() {
    const int t  = blockIdx.x;
    const int dt = blockIdx.y;
    const int pt = blockIdx.z;

    extern __shared__ uint32_t smem[];
    float acc[2][8][4];
    GemmCtx cx;
    gemm128_pipe(g_wt + dt * 16384,
                 g_xt + (size_t)t * 32768 + pt * 16384,
                 smem, acc, cx);

    const int b_ = t >> 8, s_ = t & 255;
    float* dst = (dt == 0) ? g_q : (dt == 1) ? g_k : g_v;

    #pragma unroll
    for (int mf = 0; mf < 2; mf++) {
        #pragma unroll
        for (int half = 0; half < 2; half++) {
            const int dl = cx.wm * 32 + mf * 16 + (cx.lane >> 2) + half * 8;
            const int ch = dl >> 6, cidx = dl & 63;
            #pragma unroll
            for (int nf = 0; nf < 8; nf++) {
                const int c0 = cx.wn * 64 + nf * 8 + 2 * (cx.lane & 3);
                const int p0 = pt * 128 + c0;
                const int Hi = p0 >> 4, Wi = p0 & 15;
                const int ys = Hi >> 3, hy = Hi & 7, xs = Wi >> 3, wx = Wi & 7;
                const int n = (ys * 2 + xs) * 2 + ch;
                const size_t base = ((size_t)((b_ * 8 + n) * 256 + s_)) * FDIM
                                  + cidx * 64 + hy * 8 + wx;
                float2 v = make_float2(acc[mf][nf][half * 2], acc[mf][nf][half * 2 + 1]);
                *reinterpret_cast<float2*>(dst + base) = v;
            }
        }
    }
}

// ---------------------------------------------------------------------------
// Kernel B: masked attention. One block (256 thr) per (b, head, query).
// Fixed 9-neighbor unrolled loop (register-resident arrays), float4 access.
// Epilogue writes g_sa [t][p][C] tf32 with k-permuted C layout.
// ---------------------------------------------------------------------------
__global__ __launch_bounds__(256) void attn_kernel() {
    const int idx = blockIdx.x;
    const int i   = idx & 255;
    const int n   = (idx >> 8) & 7;
    const int b_  = idx >> 11;
    const int tid = threadIdx.x;

    const size_t slice = (size_t)(b_ * 8 + n) * SLICE;

    // q: 16 contiguous floats per thread
    float4 q4[4];
    {
        const float4* qb = reinterpret_cast<const float4*>(g_q + slice + (size_t)i * FDIM) + tid * 4;
        #pragma unroll
        for (int u = 0; u < 4; u++) q4[u] = qb[u];
    }

    const int iy = i >> 4, ix = i & 15;
    int jn[9]; bool ok[9];
    #pragma unroll
    for (int e = 0; e < 9; e++) {
        const int dy = e / 3 - 1, dx = e % 3 - 1;
        const int jy = iy + dy, jx = ix + dx;
        const bool v = (jy >= 0) & (jy <= 15) & (jx >= 0) & (jx <= 15);
        ok[e] = v;
        jn[e] = v ? (jy * 16 + jx) : i;   // fallback: center (safe address)
    }

    // partial dots
    float part[9];
    #pragma unroll
    for (int e = 0; e < 9; e++) {
        const float4* kb = reinterpret_cast<const float4*>(g_k + slice + (size_t)jn[e] * FDIM) + tid * 4;
        float p = 0.f;
        #pragma unroll
        for (int u = 0; u < 4; u++) {
            float4 kv = kb[u];
            p += q4[u].x * kv.x + q4[u].y * kv.y + q4[u].z * kv.z + q4[u].w * kv.w;
        }
        part[e] = p;
    }

    // block reduction: warp shuffle then cross-warp in smem
    __shared__ float red[9][8];
    __shared__ float sm[9];
    #pragma unroll
    for (int e = 0; e < 9; e++) {
        float v = part[e];
        #pragma unroll
        for (int o = 16; o > 0; o >>= 1) v += __shfl_down_sync(0xffffffffu, v, o);
        if ((tid & 31) == 0) red[e][tid >> 5] = v;
    }
    __syncthreads();
    if (tid < 9) {
        float s = 0.f;
        #pragma unroll
        for (int w = 0; w < 8; w++) s += red[tid][w];
        sm[tid] = s * 0.015625f;   // 1/sqrt(4096)
    }
    __syncthreads();

    // softmax over the 9 (masked) scores, replicated per-thread
    float sc[9];
    float m = -1e30f;
    #pragma unroll
    for (int e = 0; e < 9; e++) { sc[e] = ok[e] ? sm[e] : -1e30f; m = fmaxf(m, sc[e]); }
    float sum = 0.f;
    #pragma unroll
    for (int e = 0; e < 9; e++) { sc[e] = __expf(sc[e] - m); sum += sc[e]; }
    const float inv = 1.0f / sum;

    // weighted sum of V
    float4 f4[4];
    #pragma unroll
    for (int u = 0; u < 4; u++) f4[u] = make_float4(0.f, 0.f, 0.f, 0.f);
    #pragma unroll
    for (int e = 0; e < 9; e++) {
        const float a = sc[e] * inv;
        const float4* vb = reinterpret_cast<const float4*>(g_v + slice + (size_t)jn[e] * FDIM) + tid * 4;
        #pragma unroll
        for (int u = 0; u < 4; u++) {
            float4 vv = vb[u];
            f4[u].x += a * vv.x; f4[u].y += a * vv.y;
            f4[u].z += a * vv.z; f4[u].w += a * vv.w;
        }
    }

    // stage: ssa[r = hy*8+wx][cidx].  thread's f = tid*16+j -> r=(tid&3)*16+j, cidx=tid>>2
    __shared__ float ssa[64][68];
    {
        const int r0 = (tid & 3) * 16, cc = tid >> 2;
        #pragma unroll
        for (int u = 0; u < 4; u++) {
            ssa[r0 + u * 4 + 0][cc] = f4[u].x;
            ssa[r0 + u * 4 + 1][cc] = f4[u].y;
            ssa[r0 + u * 4 + 2][cc] = f4[u].z;
            ssa[r0 + u * 4 + 3][cc] = f4[u].w;
        }
    }
    __syncthreads();

    // store transposed + tf32 + k-permuted. thread: r = tid>>2, 16-col chunk cb.
    // ssa columns are LOCAL cidx (0..63); gmem columns are global C = ch*64 + local.
    const int ch = n & 1, sp = n >> 1, ys = sp >> 1, xs = sp & 1;
    uint32_t* dstT = g_sa + (size_t)(b_ * 256 + i) * 32768;
    const int r  = tid >> 2;               // 0..63 local spatial
    const int cb = (tid & 3) * 16;         // local 16-col chunk base (0,16,32,48)
    const int B32g = (ch * 64 + cb) & ~31; // global 32-aligned tile base for dst
    const int h16 = (cb >> 4) & 1;         // which 16-half of the 32-tile
    const int HWp = (ys * 8 + (r >> 3)) * 16 + xs * 8 + (r & 7);
    uint32_t* rowp = dstT + (size_t)HWp * 128 + B32g;
    #pragma unroll
    for (int a = 0; a < 4; a++) {
        // permuted dst chunk [a*8 + h16*4, +4) <- LOCAL smem cols cb + 4u + a
        uint4 v;
        v.x = f2tf32(ssa[r][cb + 0  + a]);
        v.y = f2tf32(ssa[r][cb + 4  + a]);
        v.z = f2tf32(ssa[r][cb + 8  + a]);
        v.w = f2tf32(ssa[r][cb + 12 + a]);
        *reinterpret_cast<uint4*>(rowp + a * 8 + h16 * 4) = v;
    }
}

// ---------------------------------------------------------------------------
// Kernel C: output projection + bias
// ---------------------------------------------------------------------------
__global__ __launch_bounds__(256) void out_gemm(const float* __restrict__ b_out,
                                                float* __restrict__ out) {
    const int t  = blockIdx.x;
    const int pt = blockIdx.y;

    extern __shared__ uint32_t smem[];
    float acc[2][8][4];
    GemmCtx cx;
    gemm128_pipe(g_wto,
                 g_sa + (size_t)t * 32768 + pt * 16384,
                 smem, acc, cx);

    #pragma unroll
    for (int mf = 0; mf < 2; mf++) {
        #pragma unroll
        for (int half = 0; half < 2; half++) {
            const int d = cx.wm * 32 + mf * 16 + (cx.lane >> 2) + half * 8;
            const float bias = b_out[d];
            #pragma unroll
            for (int nf = 0; nf < 8; nf++) {
                const int c0 = cx.wn * 64 + nf * 8 + 2 * (cx.lane & 3);
                float2 v = make_float2(acc[mf][nf][half * 2] + bias,
                                       acc[mf][nf][half * 2 + 1] + bias);
                *reinterpret_cast<float2*>(out + (size_t)t * 32768
                                           + (size_t)d * 256 + pt * 128 + c0) = v;
            }
        }
    }
}

extern "C" void kernel_launch(void* const* d_in, const int* in_sizes, int n_in,
                              void* d_out, int out_size) {
    const float* seq   = (const float*)d_in[0];
    const float* w_qkv = (const float*)d_in[1];
    const float* w_out = (const float*)d_in[2];
    const float* b_out = (const float*)d_in[3];
    float* out = (float*)d_out;

    const int dynsmem = 73728;
    cudaFuncSetAttribute(qkv_gemm, cudaFuncAttributeMaxDynamicSharedMemorySize, dynsmem);
    cudaFuncSetAttribute(out_gemm, cudaFuncAttributeMaxDynamicSharedMemorySize, dynsmem);

    prep_w<<<192, 256>>>(w_qkv, w_out);
    prep_x<<<512, 256>>>(seq);

    dim3 gA(NTOK, 3, 2);
    qkv_gemm<<<gA, 256, dynsmem>>>();

    attn_kernel<<<4096, 256>>>();

    dim3 gC(NTOK, 2);
    out_gemm<<<gC, 256, dynsmem>>>(b_out, out);
}

// round 6
// speedup vs baseline: 1.3646x; 1.2203x over previous
#include <cuda_runtime.h>
#include <cstdint>

// Problem constants (fixed by dataset):
// b=2, s=256, C=128, H=W=16, YH=XH=CH=2 -> nH=8 heads, c=64, h=w=8, D=4096
// mask: 16x16 token grid, radius-1 neighborhood (<=9 keys per query)

#define NTOK   512
#define FDIM   4096
#define SLICE  (256*4096)

// Scratch (device globals -- allocation-free per harness rules)
__device__ float g_q[2*8*256*4096];
__device__ float g_k[2*8*256*4096];
__device__ float g_v[2*8*256*4096];
__device__ __align__(16) uint32_t g_sa[512*256*128];   // tf32 bits, [t][p][C], k-permuted
__device__ __align__(16) uint32_t g_xt[512*256*128];   // tf32 bits, [t][p][k], k-permuted
__device__ __align__(16) uint32_t g_wt[3*128*128];     // tf32 w_qkv, k-permuted
__device__ __align__(16) uint32_t g_wto[128*128];      // tf32 w_out, k-permuted

// k-permutation within each aligned 32-k tile: kperm = (k&3)*8 + (k>>2)
__device__ __forceinline__ int kperm32(int kl) { return ((kl & 3) << 3) | (kl >> 2); }

// ---------------------------------------------------------------------------
// helpers
// ---------------------------------------------------------------------------
__device__ __forceinline__ uint32_t f2tf32(float x) {
    uint32_t r;
    asm("cvt.rna.tf32.f32 %0, %1;" : "=r"(r) : "f"(x));
    return r;
}

__device__ __forceinline__ void mma_tf32(float* c,
                                         uint32_t a0, uint32_t a1, uint32_t a2, uint32_t a3,
                                         uint32_t b0, uint32_t b1) {
    asm volatile(
        "mma.sync.aligned.m16n8k8.row.col.f32.tf32.tf32.f32 "
        "{%0,%1,%2,%3}, {%4,%5,%6,%7}, {%8,%9}, {%0,%1,%2,%3};"
        : "+f"(c[0]), "+f"(c[1]), "+f"(c[2]), "+f"(c[3])
        : "r"(a0), "r"(a1), "r"(a2), "r"(a3), "r"(b0), "r"(b1));
}

__device__ __forceinline__ void cp16(uint32_t* smem_dst, const uint32_t* gsrc) {
    uint32_t s = (uint32_t)__cvta_generic_to_shared(smem_dst);
    asm volatile("cp.async.ca.shared.global [%0], [%1], 16;" :: "r"(s), "l"(gsrc));
}

// ---------------------------------------------------------------------------
// Pre-conversion kernels (write k-permuted tf32)
// ---------------------------------------------------------------------------
__global__ __launch_bounds__(256) void prep_w(const float* __restrict__ wq,
                                              const float* __restrict__ wo) {
    int i = blockIdx.x * 256 + threadIdx.x;   // grid 192
    int d = i >> 7, k = i & 127;
    int kp = (k & ~31) | kperm32(k & 31);
    g_wt[d * 128 + kp] = f2tf32(wq[i]);
    if (i < 16384) g_wto[d * 128 + kp] = f2tf32(wo[i]);
}

// transpose seq[t][c][p] -> g_xt[t][p][cperm], tf32. one block per token.
__global__ __launch_bounds__(256) void prep_x(const float* __restrict__ seq) {
    const int t = blockIdx.x;
    __shared__ float tile[32][33];
    const float* src = seq + (size_t)t * 32768;
    uint32_t* dst = g_xt + (size_t)t * 32768;

    for (int cc = 0; cc < 4; cc++)
        for (int pc = 0; pc < 8; pc++) {
            #pragma unroll
            for (int j = 0; j < 4; j++) {
                int id = threadIdx.x + j * 256;
                int r = id >> 5, cl = id & 31;
                tile[r][cl] = src[(cc * 32 + r) * 256 + pc * 32 + cl];
            }
            __syncthreads();
            #pragma unroll
            for (int j = 0; j < 4; j++) {
                int id = threadIdx.x + j * 256;
                int r = id >> 5, cl = id & 31;
                dst[(size_t)(pc * 32 + r) * 128 + cc * 32 + kperm32(cl)] = f2tf32(tile[cl][r]);
            }
            __syncthreads();
        }
}

// ---------------------------------------------------------------------------
// Pipelined tf32 GEMM core, k-permuted operands -> LDS.64 fragment loads.
// 8 warps (4x2), warp tile 32x64. K-tile 32, 2-stage cp.async.
// smem: As[2][128][36], Bs[2][128][36] u32 = 73728 B
// ---------------------------------------------------------------------------
struct GemmCtx { int lane, wm, wn; };

__device__ __forceinline__ void gemm128_pipe(
    const uint32_t* __restrict__ wmat,   // [128][128] tf32, k-permuted per 32
    const uint32_t* __restrict__ xmat,   // [128 p][128 k] tf32, k-permuted per 32
    uint32_t* smem, float acc[2][8][4], GemmCtx& cx)
{
    const int tid = threadIdx.x;
    const int lane = tid & 31, wid = tid >> 5;
    cx.lane = lane; cx.wm = wid >> 1; cx.wn = wid & 1;
    const int kq = lane & 3;
    const int rg = lane >> 2;

    #pragma unroll
    for (int mf = 0; mf < 2; mf++)
        #pragma unroll
        for (int nf = 0; nf < 8; nf++)
            #pragma unroll
            for (int r = 0; r < 4; r++) acc[mf][nf][r] = 0.f;

    auto issue = [&](int buf, int kk) {
        uint32_t* Ab = smem + buf * 4608;
        uint32_t* Bb = smem + 9216 + buf * 4608;
        #pragma unroll
        for (int i = 0; i < 4; i++) {
            int id  = tid + i * 256;            // 0..1023
            int row = id >> 3, off = id & 7;
            cp16(Ab + row * 36 + off * 4, wmat + row * 128 + kk + off * 4);
            cp16(Bb + row * 36 + off * 4, xmat + row * 128 + kk + off * 4);
        }
        asm volatile("cp.async.commit_group;" ::: "memory");
    };

    issue(0, 0);

    #pragma unroll
    for (int kt = 0; kt < 4; kt++) {
        if (kt < 3) {
            issue((kt + 1) & 1, (kt + 1) * 32);
            asm volatile("cp.async.wait_group 1;" ::: "memory");
        } else {
            asm volatile("cp.async.wait_group 0;" ::: "memory");
        }
        __syncthreads();

        const uint32_t (*As)[36] = (const uint32_t (*)[36])(smem + (kt & 1) * 4608);
        const uint32_t (*Bs)[36] = (const uint32_t (*)[36])(smem + 9216 + (kt & 1) * 4608);

        #pragma unroll
        for (int s = 0; s < 4; s++) {
            const int koff = kq * 8 + 2 * s;       // permuted: word pair = (k, k+4)
            uint2 bv[8];
            #pragma unroll
            for (int nf = 0; nf < 8; nf++) {
                int n = cx.wn * 64 + nf * 8 + rg;
                bv[nf] = *reinterpret_cast<const uint2*>(&Bs[n][koff]);
            }
            #pragma unroll
            for (int mf = 0; mf < 2; mf++) {
                int m = cx.wm * 32 + mf * 16 + rg;
                uint2 alo = *reinterpret_cast<const uint2*>(&As[m][koff]);
                uint2 ahi = *reinterpret_cast<const uint2*>(&As[m + 8][koff]);
                #pragma unroll
                for (int nf = 0; nf < 8; nf++)
                    mma_tf32(acc[mf][nf], alo.x, ahi.x, alo.y, ahi.y, bv[nf].x, bv[nf].y);
            }
        }
        __syncthreads();
    }
}

// ---------------------------------------------------------------------------
// Kernel A: QKV projection -> scatter into per-head layout g_{q,k,v}[b][n][s][f]
// ---------------------------------------------------------------------------
__global__ __launch_bounds__(256) void qkv_gemm() {
    const int t  = blockIdx.x;
    const int dt = blockIdx.y;
    const int pt = blockIdx.z;

    extern __shared__ uint32_t smem[];
    float acc[2][8][4];
    GemmCtx cx;
    gemm128_pipe(g_wt + dt * 16384,
                 g_xt + (size_t)t * 32768 + pt * 16384,
                 smem, acc, cx);

    const int b_ = t >> 8, s_ = t & 255;
    float* dst = (dt == 0) ? g_q : (dt == 1) ? g_k : g_v;

    #pragma unroll
    for (int mf = 0; mf < 2; mf++) {
        #pragma unroll
        for (int half = 0; half < 2; half++) {
            const int dl = cx.wm * 32 + mf * 16 + (cx.lane >> 2) + half * 8;
            const int ch = dl >> 6, cidx = dl & 63;
            #pragma unroll
            for (int nf = 0; nf < 8; nf++) {
                const int c0 = cx.wn * 64 + nf * 8 + 2 * (cx.lane & 3);
                const int p0 = pt * 128 + c0;
                const int Hi = p0 >> 4, Wi = p0 & 15;
                const int ys = Hi >> 3, hy = Hi & 7, xs = Wi >> 3, wx = Wi & 7;
                const int n = (ys * 2 + xs) * 2 + ch;
                const size_t base = ((size_t)((b_ * 8 + n) * 256 + s_)) * FDIM
                                  + cidx * 64 + hy * 8 + wx;
                float2 v = make_float2(acc[mf][nf][half * 2], acc[mf][nf][half * 2 + 1]);
                *reinterpret_cast<float2*>(dst + base) = v;
            }
        }
    }
}

// ---------------------------------------------------------------------------
// Kernel B: masked attention with 2x2 query tiling.
// One block (512 thr) per (b, head, 2x2 query patch): 256 blocks/slice / 4.
// Union neighborhood = 4x4 token window: each k/v tile loaded ONCE and used
// for all 4 queries (register reuse) -> 2.1x fewer L1 bytes than per-query.
// Thread owns 8 contiguous features (tid*8..+7).
// ---------------------------------------------------------------------------
__global__ __launch_bounds__(512) void attn_kernel() {
    const int blk = blockIdx.x;            // 0..1023
    const int txq = blk & 7;               // 2x2 patch x (0..7)
    const int tyq = (blk >> 3) & 7;        // 2x2 patch y
    const int n   = (blk >> 6) & 7;        // head
    const int b_  = blk >> 9;              // batch
    const int tid = threadIdx.x;           // 0..511
    const int lane = tid & 31, wid = tid >> 5;   // 16 warps

    const int qy0 = tyq * 2, qx0 = txq * 2;
    const size_t slice = (size_t)(b_ * 8 + n) * SLICE;

    // q for 4 queries, 8 contiguous feats/thread
    float4 q[4][2];
    #pragma unroll
    for (int qq = 0; qq < 4; qq++) {
        const int i = (qy0 + (qq >> 1)) * 16 + qx0 + (qq & 1);
        const float4* qb = reinterpret_cast<const float4*>(g_q + slice + (size_t)i * FDIM) + tid * 2;
        q[qq][0] = qb[0];
        q[qq][1] = qb[1];
    }

    __shared__ float red[16][4][16];   // [tile][query][warp]
    __shared__ float s_sc[16][4];
    __shared__ float s_w[4][16];
    __shared__ float ssa[64][65];      // transpose staging (one query at a time)

    const int j_safe = qy0 * 16 + qx0;

    // ---- scores: stream 16 k tiles of the 4x4 window ----
    #pragma unroll
    for (int e = 0; e < 16; e++) {
        const int ky = qy0 - 1 + (e >> 2), kx = qx0 - 1 + (e & 3);
        const bool inb = (ky >= 0) & (ky < 16) & (kx >= 0) & (kx < 16);
        const int j = inb ? (ky * 16 + kx) : j_safe;
        const float4* kb = reinterpret_cast<const float4*>(g_k + slice + (size_t)j * FDIM) + tid * 2;
        const float4 k0 = kb[0], k1 = kb[1];
        float d[4];
        #pragma unroll
        for (int qq = 0; qq < 4; qq++) {
            d[qq] = q[qq][0].x * k0.x + q[qq][0].y * k0.y + q[qq][0].z * k0.z + q[qq][0].w * k0.w
                  + q[qq][1].x * k1.x + q[qq][1].y * k1.y + q[qq][1].z * k1.z + q[qq][1].w * k1.w;
        }
        #pragma unroll
        for (int o = 16; o > 0; o >>= 1) {
            #pragma unroll
            for (int qq = 0; qq < 4; qq++) d[qq] += __shfl_down_sync(0xffffffffu, d[qq], o);
        }
        if (lane == 0) {
            #pragma unroll
            for (int qq = 0; qq < 4; qq++) red[e][qq][wid] = d[qq];
        }
    }
    __syncthreads();

    if (tid < 64) {
        const int e = tid >> 2, qq = tid & 3;
        float s = 0.f;
        #pragma unroll
        for (int w = 0; w < 16; w++) s += red[e][qq][w];
        s_sc[e][qq] = s * 0.015625f;   // 1/sqrt(4096)
    }
    __syncthreads();

    // ---- per-query masked softmax (threads 0..3) ----
    if (tid < 4) {
        const int qq = tid;
        const int qy = qy0 + (qq >> 1), qx = qx0 + (qq & 1);
        float sc[16];
        float m = -1e30f;
        #pragma unroll
        for (int e = 0; e < 16; e++) {
            const int ky = qy0 - 1 + (e >> 2), kx = qx0 - 1 + (e & 3);
            const bool valid = (ky >= 0) & (ky < 16) & (kx >= 0) & (kx < 16)
                             & (ky >= qy - 1) & (ky <= qy + 1)
                             & (kx >= qx - 1) & (kx <= qx + 1);
            sc[e] = valid ? s_sc[e][qq] : -1e30f;
            m = fmaxf(m, sc[e]);
        }
        float sum = 0.f;
        float w[16];
        #pragma unroll
        for (int e = 0; e < 16; e++) {
            w[e] = (sc[e] > -1e29f) ? __expf(sc[e] - m) : 0.f;
            sum += w[e];
        }
        const float inv = 1.0f / sum;
        #pragma unroll
        for (int e = 0; e < 16; e++) s_w[qq][e] = w[e] * inv;
    }
    __syncthreads();

    // ---- weighted V: stream 16 v tiles, apply all 4 queries' weights ----
    float4 f0[4], f1[4];
    #pragma unroll
    for (int qq = 0; qq < 4; qq++) {
        f0[qq] = make_float4(0.f, 0.f, 0.f, 0.f);
        f1[qq] = make_float4(0.f, 0.f, 0.f, 0.f);
    }
    #pragma unroll
    for (int e = 0; e < 16; e++) {
        const int ky = qy0 - 1 + (e >> 2), kx = qx0 - 1 + (e & 3);
        if ((ky < 0) | (ky >= 16) | (kx < 0) | (kx >= 16)) continue;
        const int j = ky * 16 + kx;
        const float4* vb = reinterpret_cast<const float4*>(g_v + slice + (size_t)j * FDIM) + tid * 2;
        const float4 v0 = vb[0], v1 = vb[1];
        #pragma unroll
        for (int qq = 0; qq < 4; qq++) {
            const float a = s_w[qq][e];
            f0[qq].x += a * v0.x; f0[qq].y += a * v0.y;
            f0[qq].z += a * v0.z; f0[qq].w += a * v0.w;
            f1[qq].x += a * v1.x; f1[qq].y += a * v1.y;
            f1[qq].z += a * v1.z; f1[qq].w += a * v1.w;
        }
    }

    // ---- epilogue: per query, stage transpose then tf32 + k-permuted store ----
    const int ch = n & 1, sp = n >> 1, ys = sp >> 1, xs = sp & 1;
    // staging coords: thread features f = tid*8+j -> r = f&63, cidx = f>>6
    const int sr0 = (tid & 7) * 8;         // r base (8 consecutive)
    const int scc = tid >> 3;              // cidx (0..63)
    // store coords: r = tid>>3, tile t = (tid>>2)&1, h0 = tid&3
    const int r   = tid >> 3;              // 0..63
    const int st  = (tid >> 2) & 1;        // which 32-col tile of the head's 64
    const int h0  = tid & 3;
    const int HWp = (ys * 8 + (r >> 3)) * 16 + xs * 8 + (r & 7);

    #pragma unroll
    for (int qq = 0; qq < 4; qq++) {
        __syncthreads();
        ssa[sr0 + 0][scc] = f0[qq].x;
        ssa[sr0 + 1][scc] = f0[qq].y;
        ssa[sr0 + 2][scc] = f0[qq].z;
        ssa[sr0 + 3][scc] = f0[qq].w;
        ssa[sr0 + 4][scc] = f1[qq].x;
        ssa[sr0 + 5][scc] = f1[qq].y;
        ssa[sr0 + 6][scc] = f1[qq].z;
        ssa[sr0 + 7][scc] = f1[qq].w;
        __syncthreads();

        const int i = (qy0 + (qq >> 1)) * 16 + qx0 + (qq & 1);
        uint32_t* rowp = g_sa + (size_t)(b_ * 256 + i) * 32768
                       + (size_t)HWp * 128 + ch * 64 + st * 32 + h0 * 8;
        uint4 va, vb;
        // output words p = h0*8 + a (a=0..7); source local col = st*32 + 4a + h0
        va.x = f2tf32(ssa[r][st * 32 + 0  + h0]);
        va.y = f2tf32(ssa[r][st * 32 + 4  + h0]);
        va.z = f2tf32(ssa[r][st * 32 + 8  + h0]);
        va.w = f2tf32(ssa[r][st * 32 + 12 + h0]);
        vb.x = f2tf32(ssa[r][st * 32 + 16 + h0]);
        vb.y = f2tf32(ssa[r][st * 32 + 20 + h0]);
        vb.z = f2tf32(ssa[r][st * 32 + 24 + h0]);
        vb.w = f2tf32(ssa[r][st * 32 + 28 + h0]);
        *reinterpret_cast<uint4*>(rowp)     = va;
        *reinterpret_cast<uint4*>(rowp + 4) = vb;
    }
}

// ---------------------------------------------------------------------------
// Kernel C: output projection + bias
// ---------------------------------------------------------------------------
__global__ __launch_bounds__(256) void out_gemm(const float* __restrict__ b_out,
                                                float* __restrict__ out) {
    const int t  = blockIdx.x;
    const int pt = blockIdx.y;

    extern __shared__ uint32_t smem[];
    float acc[2][8][4];
    GemmCtx cx;
    gemm128_pipe(g_wto,
                 g_sa + (size_t)t * 32768 + pt * 16384,
                 smem, acc, cx);

    #pragma unroll
    for (int mf = 0; mf < 2; mf++) {
        #pragma unroll
        for (int half = 0; half < 2; half++) {
            const int d = cx.wm * 32 + mf * 16 + (cx.lane >> 2) + half * 8;
            const float bias = b_out[d];
            #pragma unroll
            for (int nf = 0; nf < 8; nf++) {
                const int c0 = cx.wn * 64 + nf * 8 + 2 * (cx.lane & 3);
                float2 v = make_float2(acc[mf][nf][half * 2] + bias,
                                       acc[mf][nf][half * 2 + 1] + bias);
                *reinterpret_cast<float2*>(out + (size_t)t * 32768
                                           + (size_t)d * 256 + pt * 128 + c0) = v;
            }
        }
    }
}

extern "C" void kernel_launch(void* const* d_in, const int* in_sizes, int n_in,
                              void* d_out, int out_size) {
    const float* seq   = (const float*)d_in[0];
    const float* w_qkv = (const float*)d_in[1];
    const float* w_out = (const float*)d_in[2];
    const float* b_out = (const float*)d_in[3];
    float* out = (float*)d_out;

    const int dynsmem = 73728;
    cudaFuncSetAttribute(qkv_gemm, cudaFuncAttributeMaxDynamicSharedMemorySize, dynsmem);
    cudaFuncSetAttribute(out_gemm, cudaFuncAttributeMaxDynamicSharedMemorySize, dynsmem);

    prep_w<<<192, 256>>>(w_qkv, w_out);
    prep_x<<<512, 256>>>(seq);

    dim3 gA(NTOK, 3, 2);
    qkv_gemm<<<gA, 256, dynsmem>>>();

    attn_kernel<<<1024, 512>>>();

    dim3 gC(NTOK, 2);
    out_gemm<<<gC, 256, dynsmem>>>(b_out, out);
}

// round 8
// speedup vs baseline: 1.4358x; 1.0522x over previous
#include <cuda_runtime.h>
#include <cuda_fp16.h>
#include <cstdint>

// Problem constants (fixed by dataset):
// b=2, s=256, C=128, H=W=16, YH=XH=CH=2 -> nH=8 heads, c=64, h=w=8, D=4096
// mask: 16x16 token grid, radius-1 neighborhood (<=9 keys per query)

#define NTOK   512
#define FDIM   4096
#define SLICE  (256*4096)

// Scratch (device globals -- allocation-free per harness rules)
__device__ __align__(16) __half g_qh[2*8*256*4096];
__device__ __align__(16) __half g_kh[2*8*256*4096];
__device__ __align__(16) __half g_vh[2*8*256*4096];
__device__ __align__(16) uint32_t g_sa[512*256*128];   // tf32 bits, [t][p][C], k-permuted
__device__ __align__(16) uint32_t g_xt[512*256*128];   // tf32 bits, [t][p][k], k-permuted
__device__ __align__(16) uint32_t g_wt[3*128*128];     // tf32 w_qkv, k-permuted
__device__ __align__(16) uint32_t g_wto[128*128];      // tf32 w_out, k-permuted

// k-permutation within each aligned 32-k tile: kperm = (k&3)*8 + (k>>2)
__device__ __forceinline__ int kperm32(int kl) { return ((kl & 3) << 3) | (kl >> 2); }

// ---------------------------------------------------------------------------
// helpers
// ---------------------------------------------------------------------------
__device__ __forceinline__ uint32_t f2tf32(float x) {
    uint32_t r;
    asm("cvt.rna.tf32.f32 %0, %1;" : "=r"(r) : "f"(x));
    return r;
}

__device__ __forceinline__ void mma_tf32(float* c,
                                         uint32_t a0, uint32_t a1, uint32_t a2, uint32_t a3,
                                         uint32_t b0, uint32_t b1) {
    asm volatile(
        "mma.sync.aligned.m16n8k8.row.col.f32.tf32.tf32.f32 "
        "{%0,%1,%2,%3}, {%4,%5,%6,%7}, {%8,%9}, {%0,%1,%2,%3};"
        : "+f"(c[0]), "+f"(c[1]), "+f"(c[2]), "+f"(c[3])
        : "r"(a0), "r"(a1), "r"(a2), "r"(a3), "r"(b0), "r"(b1));
}

__device__ __forceinline__ void cp16(uint32_t* smem_dst, const uint32_t* gsrc) {
    uint32_t s = (uint32_t)__cvta_generic_to_shared(smem_dst);
    asm volatile("cp.async.ca.shared.global [%0], [%1], 16;" :: "r"(s), "l"(gsrc));
}

// 8 packed halfs -> 8 floats
__device__ __forceinline__ void h8tof(uint4 v, float* f) {
    float2 t;
    t = __half22float2(*reinterpret_cast<__half2*>(&v.x)); f[0] = t.x; f[1] = t.y;
    t = __half22float2(*reinterpret_cast<__half2*>(&v.y)); f[2] = t.x; f[3] = t.y;
    t = __half22float2(*reinterpret_cast<__half2*>(&v.z)); f[4] = t.x; f[5] = t.y;
    t = __half22float2(*reinterpret_cast<__half2*>(&v.w)); f[6] = t.x; f[7] = t.y;
}

// ---------------------------------------------------------------------------
// Pre-conversion kernels (write k-permuted tf32)
// ---------------------------------------------------------------------------
__global__ __launch_bounds__(256) void prep_w(const float* __restrict__ wq,
                                              const float* __restrict__ wo) {
    int i = blockIdx.x * 256 + threadIdx.x;   // grid 192
    int d = i >> 7, k = i & 127;
    int kp = (k & ~31) | kperm32(k & 31);
    g_wt[d * 128 + kp] = f2tf32(wq[i]);
    if (i < 16384) g_wto[d * 128 + kp] = f2tf32(wo[i]);
}

// transpose seq[t][c][p] -> g_xt[t][p][cperm], tf32. one block per token.
__global__ __launch_bounds__(256) void prep_x(const float* __restrict__ seq) {
    const int t = blockIdx.x;
    __shared__ float tile[32][33];
    const float* src = seq + (size_t)t * 32768;
    uint32_t* dst = g_xt + (size_t)t * 32768;

    for (int cc = 0; cc < 4; cc++)
        for (int pc = 0; pc < 8; pc++) {
            #pragma unroll
            for (int j = 0; j < 4; j++) {
                int id = threadIdx.x + j * 256;
                int r = id >> 5, cl = id & 31;
                tile[r][cl] = src[(cc * 32 + r) * 256 + pc * 32 + cl];
            }
            __syncthreads();
            #pragma unroll
            for (int j = 0; j < 4; j++) {
                int id = threadIdx.x + j * 256;
                int r = id >> 5, cl = id & 31;
                dst[(size_t)(pc * 32 + r) * 128 + cc * 32 + kperm32(cl)] = f2tf32(tile[cl][r]);
            }
            __syncthreads();
        }
}

// ---------------------------------------------------------------------------
// Pipelined tf32 GEMM core, k-permuted operands -> LDS.64 fragment loads.
// 8 warps (4x2), warp tile 32x64. K-tile 32, 2-stage cp.async.
// smem: As[2][128][36], Bs[2][128][36] u32 = 73728 B
// ---------------------------------------------------------------------------
struct GemmCtx { int lane, wm, wn; };

__device__ __forceinline__ void gemm128_pipe(
    const uint32_t* __restrict__ wmat,   // [128][128] tf32, k-permuted per 32
    const uint32_t* __restrict__ xmat,   // [128 p][128 k] tf32, k-permuted per 32
    uint32_t* smem, float acc[2][8][4], GemmCtx& cx)
{
    const int tid = threadIdx.x;
    const int lane = tid & 31, wid = tid >> 5;
    cx.lane = lane; cx.wm = wid >> 1; cx.wn = wid & 1;
    const int kq = lane & 3;
    const int rg = lane >> 2;

    #pragma unroll
    for (int mf = 0; mf < 2; mf++)
        #pragma unroll
        for (int nf = 0; nf < 8; nf++)
            #pragma unroll
            for (int r = 0; r < 4; r++) acc[mf][nf][r] = 0.f;

    auto issue = [&](int buf, int kk) {
        uint32_t* Ab = smem + buf * 4608;
        uint32_t* Bb = smem + 9216 + buf * 4608;
        #pragma unroll
        for (int i = 0; i < 4; i++) {
            int id  = tid + i * 256;            // 0..1023
            int row = id >> 3, off = id & 7;
            cp16(Ab + row * 36 + off * 4, wmat + row * 128 + kk + off * 4);
            cp16(Bb + row * 36 + off * 4, xmat + row * 128 + kk + off * 4);
        }
        asm volatile("cp.async.commit_group;" ::: "memory");
    };

    issue(0, 0);

    #pragma unroll
    for (int kt = 0; kt < 4; kt++) {
        if (kt < 3) {
            issue((kt + 1) & 1, (kt + 1) * 32);
            asm volatile("cp.async.wait_group 1;" ::: "memory");
        } else {
            asm volatile("cp.async.wait_group 0;" ::: "memory");
        }
        __syncthreads();

        const uint32_t (*As)[36] = (const uint32_t (*)[36])(smem + (kt & 1) * 4608);
        const uint32_t (*Bs)[36] = (const uint32_t (*)[36])(smem + 9216 + (kt & 1) * 4608);

        #pragma unroll
        for (int s = 0; s < 4; s++) {
            const int koff = kq * 8 + 2 * s;       // permuted: word pair = (k, k+4)
            uint2 bv[8];
            #pragma unroll
            for (int nf = 0; nf < 8; nf++) {
                int n = cx.wn * 64 + nf * 8 + rg;
                bv[nf] = *reinterpret_cast<const uint2*>(&Bs[n][koff]);
            }
            #pragma unroll
            for (int mf = 0; mf < 2; mf++) {
                int m = cx.wm * 32 + mf * 16 + rg;
                uint2 alo = *reinterpret_cast<const uint2*>(&As[m][koff]);
                uint2 ahi = *reinterpret_cast<const uint2*>(&As[m + 8][koff]);
                #pragma unroll
                for (int nf = 0; nf < 8; nf++)
                    mma_tf32(acc[mf][nf], alo.x, ahi.x, alo.y, ahi.y, bv[nf].x, bv[nf].y);
            }
        }
        __syncthreads();
    }
}

// ---------------------------------------------------------------------------
// Kernel A: QKV projection -> scatter into per-head layout (fp16 q/k/v)
// ---------------------------------------------------------------------------
__global__ __launch_bounds__(256) void qkv_gemm() {
    const int t  = blockIdx.x;
    const int dt = blockIdx.y;
    const int pt = blockIdx.z;

    extern __shared__ uint32_t smem[];
    float acc[2][8][4];
    GemmCtx cx;
    gemm128_pipe(g_wt + dt * 16384,
                 g_xt + (size_t)t * 32768 + pt * 16384,
                 smem, acc, cx);

    const int b_ = t >> 8, s_ = t & 255;
    __half* dst = (dt == 0) ? g_qh : (dt == 1) ? g_kh : g_vh;

    #pragma unroll
    for (int mf = 0; mf < 2; mf++) {
        #pragma unroll
        for (int half_ = 0; half_ < 2; half_++) {
            const int dl = cx.wm * 32 + mf * 16 + (cx.lane >> 2) + half_ * 8;
            const int ch = dl >> 6, cidx = dl & 63;
            #pragma unroll
            for (int nf = 0; nf < 8; nf++) {
                const int c0 = cx.wn * 64 + nf * 8 + 2 * (cx.lane & 3);
                const int p0 = pt * 128 + c0;
                const int Hi = p0 >> 4, Wi = p0 & 15;
                const int ys = Hi >> 3, hy = Hi & 7, xs = Wi >> 3, wx = Wi & 7;
                const int n = (ys * 2 + xs) * 2 + ch;
                const size_t base = ((size_t)((b_ * 8 + n) * 256 + s_)) * FDIM
                                  + cidx * 64 + hy * 8 + wx;
                __half2 hv = __floats2half2_rn(acc[mf][nf][half_ * 2],
                                               acc[mf][nf][half_ * 2 + 1]);
                *reinterpret_cast<__half2*>(dst + base) = hv;
            }
        }
    }
}

// ---------------------------------------------------------------------------
// Kernel B: masked attention with 2x2 query tiling, fp16 q/k/v storage.
// One block (512 thr) per (b, head, 2x2 query patch). Thread owns 8 feats.
// ---------------------------------------------------------------------------
__global__ __launch_bounds__(512) void attn_kernel() {
    const int blk = blockIdx.x;            // 0..1023
    const int txq = blk & 7;
    const int tyq = (blk >> 3) & 7;
    const int n   = (blk >> 6) & 7;
    const int b_  = blk >> 9;
    const int tid = threadIdx.x;
    const int lane = tid & 31, wid = tid >> 5;

    const int qy0 = tyq * 2, qx0 = txq * 2;
    const size_t slice = (size_t)(b_ * 8 + n) * SLICE;

    // q for 4 queries, 8 contiguous feats/thread (fp16 -> fp32 regs)
    float qf[4][8];
    #pragma unroll
    for (int qq = 0; qq < 4; qq++) {
        const int i = (qy0 + (qq >> 1)) * 16 + qx0 + (qq & 1);
        uint4 qv = *((const uint4*)(g_qh + slice + (size_t)i * FDIM) + tid);
        h8tof(qv, qf[qq]);
    }

    __shared__ float red[16][4][16];   // [tile][query][warp]
    __shared__ float s_sc[16][4];
    __shared__ float s_w[4][16];
    __shared__ float ssa[64][65];      // transpose staging (one query at a time)

    const int j_safe = qy0 * 16 + qx0;

    // ---- scores: stream 16 k tiles of the 4x4 window ----
    #pragma unroll
    for (int e = 0; e < 16; e++) {
        const int ky = qy0 - 1 + (e >> 2), kx = qx0 - 1 + (e & 3);
        const bool inb = (ky >= 0) & (ky < 16) & (kx >= 0) & (kx < 16);
        const int j = inb ? (ky * 16 + kx) : j_safe;
        uint4 kv = *((const uint4*)(g_kh + slice + (size_t)j * FDIM) + tid);
        float kf[8];
        h8tof(kv, kf);
        float d[4];
        #pragma unroll
        for (int qq = 0; qq < 4; qq++) {
            float p = 0.f;
            #pragma unroll
            for (int u = 0; u < 8; u++) p += qf[qq][u] * kf[u];
            d[qq] = p;
        }
        #pragma unroll
        for (int o = 16; o > 0; o >>= 1) {
            #pragma unroll
            for (int qq = 0; qq < 4; qq++) d[qq] += __shfl_down_sync(0xffffffffu, d[qq], o);
        }
        if (lane == 0) {
            #pragma unroll
            for (int qq = 0; qq < 4; qq++) red[e][qq][wid] = d[qq];
        }
    }
    __syncthreads();

    if (tid < 64) {
        const int e = tid >> 2, qq = tid & 3;
        float s = 0.f;
        #pragma unroll
        for (int w = 0; w < 16; w++) s += red[e][qq][w];
        s_sc[e][qq] = s * 0.015625f;   // 1/sqrt(4096)
    }
    __syncthreads();

    // ---- per-query masked softmax (threads 0..3) ----
    if (tid < 4) {
        const int qq = tid;
        const int qy = qy0 + (qq >> 1), qx = qx0 + (qq & 1);
        float sc[16];
        float m = -1e30f;
        #pragma unroll
        for (int e = 0; e < 16; e++) {
            const int ky = qy0 - 1 + (e >> 2), kx = qx0 - 1 + (e & 3);
            const bool valid = (ky >= 0) & (ky < 16) & (kx >= 0) & (kx < 16)
                             & (ky >= qy - 1) & (ky <= qy + 1)
                             & (kx >= qx - 1) & (kx <= qx + 1);
            sc[e] = valid ? s_sc[e][qq] : -1e30f;
            m = fmaxf(m, sc[e]);
        }
        float sum = 0.f;
        float w[16];
        #pragma unroll
        for (int e = 0; e < 16; e++) {
            w[e] = (sc[e] > -1e29f) ? __expf(sc[e] - m) : 0.f;
            sum += w[e];
        }
        const float inv = 1.0f / sum;
        #pragma unroll
        for (int e = 0; e < 16; e++) s_w[qq][e] = w[e] * inv;
    }
    __syncthreads();

    // ---- weighted V: stream 16 v tiles, apply all 4 queries' weights ----
    float facc[4][8];
    #pragma unroll
    for (int qq = 0; qq < 4; qq++)
        #pragma unroll
        for (int u = 0; u < 8; u++) facc[qq][u] = 0.f;

    #pragma unroll
    for (int e = 0; e < 16; e++) {
        const int ky = qy0 - 1 + (e >> 2), kx = qx0 - 1 + (e & 3);
        if ((ky < 0) | (ky >= 16) | (kx < 0) | (kx >= 16)) continue;
        const int j = ky * 16 + kx;
        uint4 vv = *((const uint4*)(g_vh + slice + (size_t)j * FDIM) + tid);
        float vf[8];
        h8tof(vv, vf);
        #pragma unroll
        for (int qq = 0; qq < 4; qq++) {
            const float a = s_w[qq][e];
            #pragma unroll
            for (int u = 0; u < 8; u++) facc[qq][u] += a * vf[u];
        }
    }

    // ---- epilogue: per query, stage transpose then tf32 + k-permuted store ----
    const int ch = n & 1, sp = n >> 1, ys = sp >> 1, xs = sp & 1;
    const int sr0 = (tid & 7) * 8;         // staging row base
    const int scc = tid >> 3;              // staging cidx
    const int r   = tid >> 3;              // 0..63 local spatial (store)
    const int st  = (tid >> 2) & 1;        // which 32-col tile of the head's 64
    const int h0  = tid & 3;
    const int HWp = (ys * 8 + (r >> 3)) * 16 + xs * 8 + (r & 7);

    #pragma unroll
    for (int qq = 0; qq < 4; qq++) {
        __syncthreads();
        #pragma unroll
        for (int u = 0; u < 8; u++) ssa[sr0 + u][scc] = facc[qq][u];
        __syncthreads();

        const int i = (qy0 + (qq >> 1)) * 16 + qx0 + (qq & 1);
        uint32_t* rowp = g_sa + (size_t)(b_ * 256 + i) * 32768
                       + (size_t)HWp * 128 + ch * 64 + st * 32 + h0 * 8;
        uint4 va, vb;
        va.x = f2tf32(ssa[r][st * 32 + 0  + h0]);
        va.y = f2tf32(ssa[r][st * 32 + 4  + h0]);
        va.z = f2tf32(ssa[r][st * 32 + 8  + h0]);
        va.w = f2tf32(ssa[r][st * 32 + 12 + h0]);
        vb.x = f2tf32(ssa[r][st * 32 + 16 + h0]);
        vb.y = f2tf32(ssa[r][st * 32 + 20 + h0]);
        vb.z = f2tf32(ssa[r][st * 32 + 24 + h0]);
        vb.w = f2tf32(ssa[r][st * 32 + 28 + h0]);
        *reinterpret_cast<uint4*>(rowp)     = va;
        *reinterpret_cast<uint4*>(rowp + 4) = vb;
    }
}

// ---------------------------------------------------------------------------
// Kernel C: output projection + bias
// ---------------------------------------------------------------------------
__global__ __launch_bounds__(256) void out_gemm(const float* __restrict__ b_out,
                                                float* __restrict__ out) {
    const int t  = blockIdx.x;
    const int pt = blockIdx.y;

    extern __shared__ uint32_t smem[];
    float acc[2][8][4];
    GemmCtx cx;
    gemm128_pipe(g_wto,
                 g_sa + (size_t)t * 32768 + pt * 16384,
                 smem, acc, cx);

    #pragma unroll
    for (int mf = 0; mf < 2; mf++) {
        #pragma unroll
        for (int half_ = 0; half_ < 2; half_++) {
            const int d = cx.wm * 32 + mf * 16 + (cx.lane >> 2) + half_ * 8;
            const float bias = b_out[d];
            #pragma unroll
            for (int nf = 0; nf < 8; nf++) {
                const int c0 = cx.wn * 64 + nf * 8 + 2 * (cx.lane & 3);
                float2 v = make_float2(acc[mf][nf][half_ * 2] + bias,
                                       acc[mf][nf][half_ * 2 + 1] + bias);
                *reinterpret_cast<float2*>(out + (size_t)t * 32768
                                           + (size_t)d * 256 + pt * 128 + c0) = v;
            }
        }
    }
}

extern "C" void kernel_launch(void* const* d_in, const int* in_sizes, int n_in,
                              void* d_out, int out_size) {
    const float* seq   = (const float*)d_in[0];
    const float* w_qkv = (const float*)d_in[1];
    const float* w_out = (const float*)d_in[2];
    const float* b_out = (const float*)d_in[3];
    float* out = (float*)d_out;

    const int dynsmem = 73728;
    cudaFuncSetAttribute(qkv_gemm, cudaFuncAttributeMaxDynamicSharedMemorySize, dynsmem);
    cudaFuncSetAttribute(out_gemm, cudaFuncAttributeMaxDynamicSharedMemorySize, dynsmem);

    prep_w<<<192, 256>>>(w_qkv, w_out);
    prep_x<<<512, 256>>>(seq);

    dim3 gA(NTOK, 3, 2);
    qkv_gemm<<<gA, 256, dynsmem>>>();

    attn_kernel<<<1024, 512>>>();

    dim3 gC(NTOK, 2);
    out_gemm<<<gC, 256, dynsmem>>>(b_out, out);
}

// round 9
// speedup vs baseline: 1.4386x; 1.0020x over previous
#include <cuda_runtime.h>
#include <cuda_fp16.h>
#include <cstdint>

// Problem constants (fixed by dataset):
// b=2, s=256, C=128, H=W=16, YH=XH=CH=2 -> nH=8 heads, c=64, h=w=8, D=4096
// mask: 16x16 token grid, radius-1 neighborhood (<=9 keys per query)

#define NTOK   512
#define FDIM   4096
#define SLICE  (256*4096)

typedef unsigned long long u64;

// Scratch (device globals -- allocation-free per harness rules)
__device__ __align__(16) __half g_qh[2*8*256*4096];
__device__ __align__(16) __half g_kh[2*8*256*4096];
__device__ __align__(16) __half g_vh[2*8*256*4096];
__device__ __align__(16) uint32_t g_sa[512*256*128];   // tf32 bits, [t][p][C], k-permuted
__device__ __align__(16) uint32_t g_xt[512*256*128];   // tf32 bits, [t][p][k], k-permuted
__device__ __align__(16) uint32_t g_wt[3*128*128];     // tf32 w_qkv, k-permuted
__device__ __align__(16) uint32_t g_wto[128*128];      // tf32 w_out, k-permuted

// k-permutation within each aligned 32-k tile: kperm = (k&3)*8 + (k>>2)
__device__ __forceinline__ int kperm32(int kl) { return ((kl & 3) << 3) | (kl >> 2); }

// ---------------------------------------------------------------------------
// helpers
// ---------------------------------------------------------------------------
__device__ __forceinline__ uint32_t f2tf32(float x) {
    uint32_t r;
    asm("cvt.rna.tf32.f32 %0, %1;" : "=r"(r) : "f"(x));
    return r;
}

__device__ __forceinline__ void mma_tf32(float* c,
                                         uint32_t a0, uint32_t a1, uint32_t a2, uint32_t a3,
                                         uint32_t b0, uint32_t b1) {
    asm volatile(
        "mma.sync.aligned.m16n8k8.row.col.f32.tf32.tf32.f32 "
        "{%0,%1,%2,%3}, {%4,%5,%6,%7}, {%8,%9}, {%0,%1,%2,%3};"
        : "+f"(c[0]), "+f"(c[1]), "+f"(c[2]), "+f"(c[3])
        : "r"(a0), "r"(a1), "r"(a2), "r"(a3), "r"(b0), "r"(b1));
}

__device__ __forceinline__ void cp16(uint32_t* smem_dst, const uint32_t* gsrc) {
    uint32_t s = (uint32_t)__cvta_generic_to_shared(smem_dst);
    asm volatile("cp.async.ca.shared.global [%0], [%1], 16;" :: "r"(s), "l"(gsrc));
}

// ---- packed fp32 (B300 FFMA2 path) ----
__device__ __forceinline__ u64 pack2(float x, float y) {
    u64 r;
    asm("mov.b64 %0, {%1, %2};" : "=l"(r) : "f"(x), "f"(y));
    return r;
}
__device__ __forceinline__ void unpack2(u64 v, float& x, float& y) {
    asm("mov.b64 {%0, %1}, %2;" : "=f"(x), "=f"(y) : "l"(v));
}
__device__ __forceinline__ u64 ffma2(u64 a, u64 b, u64 c) {
    u64 d;
    asm("fma.rn.f32x2 %0, %1, %2, %3;" : "=l"(d) : "l"(a), "l"(b), "l"(c));
    return d;
}
// half2 bits -> packed f32x2
__device__ __forceinline__ u64 h2tofx2(uint32_t h2bits) {
    float2 f = __half22float2(*reinterpret_cast<__half2*>(&h2bits));
    return pack2(f.x, f.y);
}

// ---------------------------------------------------------------------------
// Pre-conversion kernels (write k-permuted tf32)
// ---------------------------------------------------------------------------
__global__ __launch_bounds__(256) void prep_w(const float* __restrict__ wq,
                                              const float* __restrict__ wo) {
    int i = blockIdx.x * 256 + threadIdx.x;   // grid 192
    int d = i >> 7, k = i & 127;
    int kp = (k & ~31) | kperm32(k & 31);
    g_wt[d * 128 + kp] = f2tf32(wq[i]);
    if (i < 16384) g_wto[d * 128 + kp] = f2tf32(wo[i]);
}

// transpose seq[t][c][p] -> g_xt[t][p][cperm], tf32. one block per token.
__global__ __launch_bounds__(256) void prep_x(const float* __restrict__ seq) {
    const int t = blockIdx.x;
    __shared__ float tile[32][33];
    const float* src = seq + (size_t)t * 32768;
    uint32_t* dst = g_xt + (size_t)t * 32768;

    for (int cc = 0; cc < 4; cc++)
        for (int pc = 0; pc < 8; pc++) {
            #pragma unroll
            for (int j = 0; j < 4; j++) {
                int id = threadIdx.x + j * 256;
                int r = id >> 5, cl = id & 31;
                tile[r][cl] = src[(cc * 32 + r) * 256 + pc * 32 + cl];
            }
            __syncthreads();
            #pragma unroll
            for (int j = 0; j < 4; j++) {
                int id = threadIdx.x + j * 256;
                int r = id >> 5, cl = id & 31;
                dst[(size_t)(pc * 32 + r) * 128 + cc * 32 + kperm32(cl)] = f2tf32(tile[cl][r]);
            }
            __syncthreads();
        }
}

// ---------------------------------------------------------------------------
// Pipelined tf32 GEMM core, k-permuted operands -> LDS.64 fragment loads.
// ---------------------------------------------------------------------------
struct GemmCtx { int lane, wm, wn; };

__device__ __forceinline__ void gemm128_pipe(
    const uint32_t* __restrict__ wmat,
    const uint32_t* __restrict__ xmat,
    uint32_t* smem, float acc[2][8][4], GemmCtx& cx)
{
    const int tid = threadIdx.x;
    const int lane = tid & 31, wid = tid >> 5;
    cx.lane = lane; cx.wm = wid >> 1; cx.wn = wid & 1;
    const int kq = lane & 3;
    const int rg = lane >> 2;

    #pragma unroll
    for (int mf = 0; mf < 2; mf++)
        #pragma unroll
        for (int nf = 0; nf < 8; nf++)
            #pragma unroll
            for (int r = 0; r < 4; r++) acc[mf][nf][r] = 0.f;

    auto issue = [&](int buf, int kk) {
        uint32_t* Ab = smem + buf * 4608;
        uint32_t* Bb = smem + 9216 + buf * 4608;
        #pragma unroll
        for (int i = 0; i < 4; i++) {
            int id  = tid + i * 256;
            int row = id >> 3, off = id & 7;
            cp16(Ab + row * 36 + off * 4, wmat + row * 128 + kk + off * 4);
            cp16(Bb + row * 36 + off * 4, xmat + row * 128 + kk + off * 4);
        }
        asm volatile("cp.async.commit_group;" ::: "memory");
    };

    issue(0, 0);

    #pragma unroll
    for (int kt = 0; kt < 4; kt++) {
        if (kt < 3) {
            issue((kt + 1) & 1, (kt + 1) * 32);
            asm volatile("cp.async.wait_group 1;" ::: "memory");
        } else {
            asm volatile("cp.async.wait_group 0;" ::: "memory");
        }
        __syncthreads();

        const uint32_t (*As)[36] = (const uint32_t (*)[36])(smem + (kt & 1) * 4608);
        const uint32_t (*Bs)[36] = (const uint32_t (*)[36])(smem + 9216 + (kt & 1) * 4608);

        #pragma unroll
        for (int s = 0; s < 4; s++) {
            const int koff = kq * 8 + 2 * s;
            uint2 bv[8];
            #pragma unroll
            for (int nf = 0; nf < 8; nf++) {
                int n = cx.wn * 64 + nf * 8 + rg;
                bv[nf] = *reinterpret_cast<const uint2*>(&Bs[n][koff]);
            }
            #pragma unroll
            for (int mf = 0; mf < 2; mf++) {
                int m = cx.wm * 32 + mf * 16 + rg;
                uint2 alo = *reinterpret_cast<const uint2*>(&As[m][koff]);
                uint2 ahi = *reinterpret_cast<const uint2*>(&As[m + 8][koff]);
                #pragma unroll
                for (int nf = 0; nf < 8; nf++)
                    mma_tf32(acc[mf][nf], alo.x, ahi.x, alo.y, ahi.y, bv[nf].x, bv[nf].y);
            }
        }
        __syncthreads();
    }
}

// ---------------------------------------------------------------------------
// Kernel A: QKV projection -> per-head fp16 layout.
// grid (3, 512, 2): x=dt so consecutive blocks reuse the same X tile via L2.
// ---------------------------------------------------------------------------
__global__ __launch_bounds__(256) void qkv_gemm() {
    const int dt = blockIdx.x;
    const int t  = blockIdx.y;
    const int pt = blockIdx.z;

    extern __shared__ uint32_t smem[];
    float acc[2][8][4];
    GemmCtx cx;
    gemm128_pipe(g_wt + dt * 16384,
                 g_xt + (size_t)t * 32768 + pt * 16384,
                 smem, acc, cx);

    const int b_ = t >> 8, s_ = t & 255;
    __half* dst = (dt == 0) ? g_qh : (dt == 1) ? g_kh : g_vh;

    #pragma unroll
    for (int mf = 0; mf < 2; mf++) {
        #pragma unroll
        for (int half_ = 0; half_ < 2; half_++) {
            const int dl = cx.wm * 32 + mf * 16 + (cx.lane >> 2) + half_ * 8;
            const int ch = dl >> 6, cidx = dl & 63;
            #pragma unroll
            for (int nf = 0; nf < 8; nf++) {
                const int c0 = cx.wn * 64 + nf * 8 + 2 * (cx.lane & 3);
                const int p0 = pt * 128 + c0;
                const int Hi = p0 >> 4, Wi = p0 & 15;
                const int ys = Hi >> 3, hy = Hi & 7, xs = Wi >> 3, wx = Wi & 7;
                const int n = (ys * 2 + xs) * 2 + ch;
                const size_t base = ((size_t)((b_ * 8 + n) * 256 + s_)) * FDIM
                                  + cidx * 64 + hy * 8 + wx;
                __half2 hv = __floats2half2_rn(acc[mf][nf][half_ * 2],
                                               acc[mf][nf][half_ * 2 + 1]);
                *reinterpret_cast<__half2*>(dst + base) = hv;
            }
        }
    }
}

// ---------------------------------------------------------------------------
// Kernel B: masked attention, 2x2 query tiling, fp16 storage, packed f32x2 math.
// One block (512 thr) per (b, head, 2x2 query patch). Thread owns 8 feats.
// Dynamic smem: red[16][4][16] | s_sc[16][4] | s_w[4][16] | ssa[4][64][65]
// ---------------------------------------------------------------------------
__global__ __launch_bounds__(512, 2) void attn_kernel() {
    const int blk = blockIdx.x;            // 0..1023
    const int txq = blk & 7;
    const int tyq = (blk >> 3) & 7;
    const int n   = (blk >> 6) & 7;
    const int b_  = blk >> 9;
    const int tid = threadIdx.x;
    const int lane = tid & 31, wid = tid >> 5;

    extern __shared__ float smf[];
    float (*red)[4][16]  = (float (*)[4][16])smf;           // 1024 floats
    float (*s_sc)[4]     = (float (*)[4])(smf + 1024);      // 64
    float (*s_w)[16]     = (float (*)[16])(smf + 1088);     // 64
    float (*ssa)[64][65] = (float (*)[64][65])(smf + 1152); // 16640

    const int qy0 = tyq * 2, qx0 = txq * 2;
    const size_t slice = (size_t)(b_ * 8 + n) * SLICE;

    // q for 4 queries, 8 contiguous feats/thread as 4 packed f32x2 each
    u64 qp[4][4];
    #pragma unroll
    for (int qq = 0; qq < 4; qq++) {
        const int i = (qy0 + (qq >> 1)) * 16 + qx0 + (qq & 1);
        uint4 qv = *((const uint4*)(g_qh + slice + (size_t)i * FDIM) + tid);
        qp[qq][0] = h2tofx2(qv.x); qp[qq][1] = h2tofx2(qv.y);
        qp[qq][2] = h2tofx2(qv.z); qp[qq][3] = h2tofx2(qv.w);
    }

    const int j_safe = qy0 * 16 + qx0;

    // ---- scores: stream 16 k tiles of the 4x4 window (FFMA2 dots) ----
    #pragma unroll
    for (int e = 0; e < 16; e++) {
        const int ky = qy0 - 1 + (e >> 2), kx = qx0 - 1 + (e & 3);
        const bool inb = (ky >= 0) & (ky < 16) & (kx >= 0) & (kx < 16);
        const int j = inb ? (ky * 16 + kx) : j_safe;
        uint4 kv = *((const uint4*)(g_kh + slice + (size_t)j * FDIM) + tid);
        u64 kp[4];
        kp[0] = h2tofx2(kv.x); kp[1] = h2tofx2(kv.y);
        kp[2] = h2tofx2(kv.z); kp[3] = h2tofx2(kv.w);
        float d[4];
        #pragma unroll
        for (int qq = 0; qq < 4; qq++) {
            u64 d2 = 0ull;
            #pragma unroll
            for (int u = 0; u < 4; u++) d2 = ffma2(qp[qq][u], kp[u], d2);
            float lo, hi;
            unpack2(d2, lo, hi);
            d[qq] = lo + hi;
        }
        #pragma unroll
        for (int o = 16; o > 0; o >>= 1) {
            #pragma unroll
            for (int qq = 0; qq < 4; qq++) d[qq] += __shfl_down_sync(0xffffffffu, d[qq], o);
        }
        if (lane == 0) {
            #pragma unroll
            for (int qq = 0; qq < 4; qq++) red[e][qq][wid] = d[qq];
        }
    }
    __syncthreads();

    if (tid < 64) {
        const int e = tid >> 2, qq = tid & 3;
        float s = 0.f;
        #pragma unroll
        for (int w = 0; w < 16; w++) s += red[e][qq][w];
        s_sc[e][qq] = s * 0.015625f;   // 1/sqrt(4096)
    }
    __syncthreads();

    // ---- per-query masked softmax (threads 0..3) ----
    if (tid < 4) {
        const int qq = tid;
        const int qy = qy0 + (qq >> 1), qx = qx0 + (qq & 1);
        float sc[16];
        float m = -1e30f;
        #pragma unroll
        for (int e = 0; e < 16; e++) {
            const int ky = qy0 - 1 + (e >> 2), kx = qx0 - 1 + (e & 3);
            const bool valid = (ky >= 0) & (ky < 16) & (kx >= 0) & (kx < 16)
                             & (ky >= qy - 1) & (ky <= qy + 1)
                             & (kx >= qx - 1) & (kx <= qx + 1);
            sc[e] = valid ? s_sc[e][qq] : -1e30f;
            m = fmaxf(m, sc[e]);
        }
        float sum = 0.f;
        float w[16];
        #pragma unroll
        for (int e = 0; e < 16; e++) {
            w[e] = (sc[e] > -1e29f) ? __expf(sc[e] - m) : 0.f;
            sum += w[e];
        }
        const float inv = 1.0f / sum;
        #pragma unroll
        for (int e = 0; e < 16; e++) s_w[qq][e] = w[e] * inv;
    }
    __syncthreads();

    // ---- weighted V: stream 16 v tiles (FFMA2 accumulate) ----
    u64 fa[4][4];
    #pragma unroll
    for (int qq = 0; qq < 4; qq++)
        #pragma unroll
        for (int u = 0; u < 4; u++) fa[qq][u] = 0ull;

    #pragma unroll
    for (int e = 0; e < 16; e++) {
        const int ky = qy0 - 1 + (e >> 2), kx = qx0 - 1 + (e & 3);
        if ((ky < 0) | (ky >= 16) | (kx < 0) | (kx >= 16)) continue;
        const int j = ky * 16 + kx;
        uint4 vv = *((const uint4*)(g_vh + slice + (size_t)j * FDIM) + tid);
        u64 vp[4];
        vp[0] = h2tofx2(vv.x); vp[1] = h2tofx2(vv.y);
        vp[2] = h2tofx2(vv.z); vp[3] = h2tofx2(vv.w);
        #pragma unroll
        for (int qq = 0; qq < 4; qq++) {
            const float a = s_w[qq][e];
            const u64 a2 = pack2(a, a);
            #pragma unroll
            for (int u = 0; u < 4; u++) fa[qq][u] = ffma2(a2, vp[u], fa[qq][u]);
        }
    }

    // ---- epilogue: all 4 queries staged at once, ONE barrier ----
    const int ch = n & 1, sp = n >> 1, ys = sp >> 1, xs = sp & 1;
    const int sr0 = (tid & 7) * 8;         // staging row base
    const int scc = tid >> 3;              // staging cidx
    const int r   = tid >> 3;              // 0..63 local spatial (store)
    const int st  = (tid >> 2) & 1;        // which 32-col tile of the head's 64
    const int h0  = tid & 3;
    const int HWp = (ys * 8 + (r >> 3)) * 16 + xs * 8 + (r & 7);

    #pragma unroll
    for (int qq = 0; qq < 4; qq++) {
        #pragma unroll
        for (int u = 0; u < 4; u++) {
            float lo, hi;
            unpack2(fa[qq][u], lo, hi);
            ssa[qq][sr0 + 2 * u    ][scc] = lo;
            ssa[qq][sr0 + 2 * u + 1][scc] = hi;
        }
    }
    __syncthreads();

    #pragma unroll
    for (int qq = 0; qq < 4; qq++) {
        const int i = (qy0 + (qq >> 1)) * 16 + qx0 + (qq & 1);
        uint32_t* rowp = g_sa + (size_t)(b_ * 256 + i) * 32768
                       + (size_t)HWp * 128 + ch * 64 + st * 32 + h0 * 8;
        uint4 va, vb;
        va.x = f2tf32(ssa[qq][r][st * 32 + 0  + h0]);
        va.y = f2tf32(ssa[qq][r][st * 32 + 4  + h0]);
        va.z = f2tf32(ssa[qq][r][st * 32 + 8  + h0]);
        va.w = f2tf32(ssa[qq][r][st * 32 + 12 + h0]);
        vb.x = f2tf32(ssa[qq][r][st * 32 + 16 + h0]);
        vb.y = f2tf32(ssa[qq][r][st * 32 + 20 + h0]);
        vb.z = f2tf32(ssa[qq][r][st * 32 + 24 + h0]);
        vb.w = f2tf32(ssa[qq][r][st * 32 + 28 + h0]);
        *reinterpret_cast<uint4*>(rowp)     = va;
        *reinterpret_cast<uint4*>(rowp + 4) = vb;
    }
}

// ---------------------------------------------------------------------------
// Kernel C: output projection + bias
// ---------------------------------------------------------------------------
__global__ __launch_bounds__(256) void out_gemm(const float* __restrict__ b_out,
                                                float* __restrict__ out) {
    const int t  = blockIdx.x;
    const int pt = blockIdx.y;

    extern __shared__ uint32_t smem[];
    float acc[2][8][4];
    GemmCtx cx;
    gemm128_pipe(g_wto,
                 g_sa + (size_t)t * 32768 + pt * 16384,
                 smem, acc, cx);

    #pragma unroll
    for (int mf = 0; mf < 2; mf++) {
        #pragma unroll
        for (int half_ = 0; half_ < 2; half_++) {
            const int d = cx.wm * 32 + mf * 16 + (cx.lane >> 2) + half_ * 8;
            const float bias = b_out[d];
            #pragma unroll
            for (int nf = 0; nf < 8; nf++) {
                const int c0 = cx.wn * 64 + nf * 8 + 2 * (cx.lane & 3);
                float2 v = make_float2(acc[mf][nf][half_ * 2] + bias,
                                       acc[mf][nf][half_ * 2 + 1] + bias);
                *reinterpret_cast<float2*>(out + (size_t)t * 32768
                                           + (size_t)d * 256 + pt * 128 + c0) = v;
            }
        }
    }
}

extern "C" void kernel_launch(void* const* d_in, const int* in_sizes, int n_in,
                              void* d_out, int out_size) {
    const float* seq   = (const float*)d_in[0];
    const float* w_qkv = (const float*)d_in[1];
    const float* w_out = (const float*)d_in[2];
    const float* b_out = (const float*)d_in[3];
    float* out = (float*)d_out;

    const int dynsmem = 73728;
    const int attnsmem = 71168;
    cudaFuncSetAttribute(qkv_gemm, cudaFuncAttributeMaxDynamicSharedMemorySize, dynsmem);
    cudaFuncSetAttribute(out_gemm, cudaFuncAttributeMaxDynamicSharedMemorySize, dynsmem);
    cudaFuncSetAttribute(attn_kernel, cudaFuncAttributeMaxDynamicSharedMemorySize, attnsmem);

    prep_w<<<192, 256>>>(w_qkv, w_out);
    prep_x<<<512, 256>>>(seq);

    dim3 gA(3, NTOK, 2);
    qkv_gemm<<<gA, 256, dynsmem>>>();

    attn_kernel<<<1024, 512, attnsmem>>>();

    dim3 gC(NTOK, 2);
    out_gemm<<<gC, 256, dynsmem>>>(b_out, out);
}

// round 10
// speedup vs baseline: 2.3270x; 1.6175x over previous
#include <cuda_runtime.h>
#include <cuda_fp16.h>
#include <cstdint>

// Problem constants (fixed by dataset):
// b=2, s=256, C=128, H=W=16, YH=XH=CH=2 -> nH=8 heads, c=64, h=w=8, D=4096
// mask: 16x16 token grid, radius-1 neighborhood (<=9 keys per query)

#define NTOK   512
#define FDIM   4096
#define SLICE  (256*4096)
#define PITCH  72            // smem row pitch in halfs (64 data + 8 pad)

typedef unsigned long long u64;

// Scratch (device globals -- allocation-free per harness rules)
__device__ __align__(16) __half g_qh[2*8*256*4096];
__device__ __align__(16) __half g_kh[2*8*256*4096];
__device__ __align__(16) __half g_vh[2*8*256*4096];
__device__ __align__(16) __half g_sah[512*256*128];   // fp16 sa, [t][p][C]
__device__ __align__(16) __half g_xth[512*256*128];   // fp16 seq^T, [t][p][c]
__device__ __align__(16) __half g_wth[3*128*128];     // fp16 w_qkv [d][k]
__device__ __align__(16) __half g_wtoh[128*128];      // fp16 w_out [d][k]

// ---------------------------------------------------------------------------
// helpers
// ---------------------------------------------------------------------------
__device__ __forceinline__ void cp16h(__half* smem_dst, const __half* gsrc) {
    uint32_t s = (uint32_t)__cvta_generic_to_shared(smem_dst);
    asm volatile("cp.async.ca.shared.global [%0], [%1], 16;" :: "r"(s), "l"(gsrc));
}

__device__ __forceinline__ void ldsm4(uint32_t* r, const __half* p) {
    uint32_t a = (uint32_t)__cvta_generic_to_shared(p);
    asm volatile("ldmatrix.sync.aligned.m8n8.x4.shared.b16 {%0,%1,%2,%3}, [%4];"
                 : "=r"(r[0]), "=r"(r[1]), "=r"(r[2]), "=r"(r[3]) : "r"(a));
}

__device__ __forceinline__ void mma_f16(float* c, const uint32_t* a,
                                        uint32_t b0, uint32_t b1) {
    asm volatile(
        "mma.sync.aligned.m16n8k16.row.col.f32.f16.f16.f32 "
        "{%0,%1,%2,%3}, {%4,%5,%6,%7}, {%8,%9}, {%0,%1,%2,%3};"
        : "+f"(c[0]), "+f"(c[1]), "+f"(c[2]), "+f"(c[3])
        : "r"(a[0]), "r"(a[1]), "r"(a[2]), "r"(a[3]), "r"(b0), "r"(b1));
}

// ---- packed fp32 (B300 FFMA2 path) ----
__device__ __forceinline__ u64 pack2(float x, float y) {
    u64 r;
    asm("mov.b64 %0, {%1, %2};" : "=l"(r) : "f"(x), "f"(y));
    return r;
}
__device__ __forceinline__ void unpack2(u64 v, float& x, float& y) {
    asm("mov.b64 {%0, %1}, %2;" : "=f"(x), "=f"(y) : "l"(v));
}
__device__ __forceinline__ u64 ffma2(u64 a, u64 b, u64 c) {
    u64 d;
    asm("fma.rn.f32x2 %0, %1, %2, %3;" : "=l"(d) : "l"(a), "l"(b), "l"(c));
    return d;
}
__device__ __forceinline__ u64 h2tofx2(uint32_t h2bits) {
    float2 f = __half22float2(*reinterpret_cast<__half2*>(&h2bits));
    return pack2(f.x, f.y);
}

// ---------------------------------------------------------------------------
// Pre-conversion kernels (plain fp16, row-major, no permutation)
// ---------------------------------------------------------------------------
__global__ __launch_bounds__(256) void prep_w(const float* __restrict__ wq,
                                              const float* __restrict__ wo) {
    int i = blockIdx.x * 256 + threadIdx.x;   // grid 192 -> 49152
    g_wth[i] = __float2half_rn(wq[i]);
    if (i < 16384) g_wtoh[i] = __float2half_rn(wo[i]);
}

// transpose seq[t][c][p] -> g_xth[t][p][c] fp16. one block per token.
__global__ __launch_bounds__(256) void prep_x(const float* __restrict__ seq) {
    const int t = blockIdx.x;
    __shared__ float tile[32][33];
    const float* src = seq + (size_t)t * 32768;
    __half* dst = g_xth + (size_t)t * 32768;

    for (int cc = 0; cc < 4; cc++)
        for (int pc = 0; pc < 8; pc++) {
            #pragma unroll
            for (int j = 0; j < 4; j++) {
                int id = threadIdx.x + j * 256;
                int r = id >> 5, cl = id & 31;
                tile[r][cl] = src[(cc * 32 + r) * 256 + pc * 32 + cl];
            }
            __syncthreads();
            #pragma unroll
            for (int j = 0; j < 4; j++) {
                int id = threadIdx.x + j * 256;
                int r = id >> 5, cl = id & 31;
                dst[(size_t)(pc * 32 + r) * 128 + cc * 32 + cl] = __float2half_rn(tile[cl][r]);
            }
            __syncthreads();
        }
}

// ---------------------------------------------------------------------------
// fp16 GEMM core: C[128,128] = W[128,128] * X^T (X rows [p][k], k contiguous).
// 8 warps (4x2), warp tile 32x64 = 2x8 m16n8k16. Two 64-K tiles, both
// prefetched via cp.async; ldmatrix.x4 fragment loads (conflict-free, pitch 72).
// smem: 2 stages x (A[128][72] + B[128][72]) halfs = 73728 B
// ---------------------------------------------------------------------------
struct GemmCtx { int lane, wm, wn; };

__device__ __forceinline__ void gemm128_f16(
    const __half* __restrict__ wmat,   // [128][128] fp16
    const __half* __restrict__ xmat,   // [128 p][128 k] fp16
    __half* smem, float acc[2][8][4], GemmCtx& cx)
{
    const int tid = threadIdx.x;
    const int lane = tid & 31, wid = tid >> 5;
    cx.lane = lane; cx.wm = wid >> 1; cx.wn = wid & 1;

    #pragma unroll
    for (int mf = 0; mf < 2; mf++)
        #pragma unroll
        for (int nf = 0; nf < 8; nf++)
            #pragma unroll
            for (int r = 0; r < 4; r++) acc[mf][nf][r] = 0.f;

    auto issue = [&](int buf, int kk) {
        __half* Ab = smem + buf * 18432;
        __half* Bb = Ab + 9216;
        #pragma unroll
        for (int i = 0; i < 4; i++) {
            int id  = tid + i * 256;        // 0..1023
            int row = id >> 3, seg = (id & 7) * 8;
            cp16h(Ab + row * PITCH + seg, wmat + row * 128 + kk + seg);
            cp16h(Bb + row * PITCH + seg, xmat + row * 128 + kk + seg);
        }
        asm volatile("cp.async.commit_group;" ::: "memory");
    };

    issue(0, 0);
    issue(1, 64);

    // per-lane ldmatrix address components
    const int l7 = lane & 7;
    const int aoff = (l7 + ((lane >> 3) & 1) * 8) * PITCH + ((lane >> 4) & 1) * 8;
    const int boff = (l7 + ((lane >> 4) & 1) * 8) * PITCH + ((lane >> 3) & 1) * 8;

    #pragma unroll
    for (int kt = 0; kt < 2; kt++) {
        if (kt == 0) {
            asm volatile("cp.async.wait_group 1;" ::: "memory");
        } else {
            asm volatile("cp.async.wait_group 0;" ::: "memory");
        }
        __syncthreads();

        const __half* A = smem + kt * 18432;
        const __half* B = A + 9216;

        #pragma unroll
        for (int k0 = 0; k0 < 64; k0 += 16) {
            uint32_t af[2][4], bf[4][4];
            #pragma unroll
            for (int mf = 0; mf < 2; mf++)
                ldsm4(af[mf], A + (cx.wm * 32 + mf * 16) * PITCH + k0 + aoff);
            #pragma unroll
            for (int np = 0; np < 4; np++)
                ldsm4(bf[np], B + (cx.wn * 64 + np * 16) * PITCH + k0 + boff);
            #pragma unroll
            for (int mf = 0; mf < 2; mf++)
                #pragma unroll
                for (int nf = 0; nf < 8; nf++)
                    mma_f16(acc[mf][nf], af[mf],
                            bf[nf >> 1][(nf & 1) * 2], bf[nf >> 1][(nf & 1) * 2 + 1]);
        }
    }
}

// ---------------------------------------------------------------------------
// Kernel A: QKV projection -> per-head fp16 layout.
// grid (3, 512, 2): x=dt so consecutive blocks reuse the same X tile via L2.
// ---------------------------------------------------------------------------
__global__ __launch_bounds__(256, 2) void qkv_gemm() {
    const int dt = blockIdx.x;
    const int t  = blockIdx.y;
    const int pt = blockIdx.z;

    extern __shared__ __align__(16) __half smem[];
    float acc[2][8][4];
    GemmCtx cx;
    gemm128_f16(g_wth + dt * 16384,
                g_xth + (size_t)t * 32768 + pt * 16384,
                smem, acc, cx);

    const int b_ = t >> 8, s_ = t & 255;
    __half* dst = (dt == 0) ? g_qh : (dt == 1) ? g_kh : g_vh;

    #pragma unroll
    for (int mf = 0; mf < 2; mf++) {
        #pragma unroll
        for (int half_ = 0; half_ < 2; half_++) {
            const int dl = cx.wm * 32 + mf * 16 + (cx.lane >> 2) + half_ * 8;
            const int ch = dl >> 6, cidx = dl & 63;
            #pragma unroll
            for (int nf = 0; nf < 8; nf++) {
                const int c0 = cx.wn * 64 + nf * 8 + 2 * (cx.lane & 3);
                const int p0 = pt * 128 + c0;
                const int Hi = p0 >> 4, Wi = p0 & 15;
                const int ys = Hi >> 3, hy = Hi & 7, xs = Wi >> 3, wx = Wi & 7;
                const int n = (ys * 2 + xs) * 2 + ch;
                const size_t base = ((size_t)((b_ * 8 + n) * 256 + s_)) * FDIM
                                  + cidx * 64 + hy * 8 + wx;
                __half2 hv = __floats2half2_rn(acc[mf][nf][half_ * 2],
                                               acc[mf][nf][half_ * 2 + 1]);
                *reinterpret_cast<__half2*>(dst + base) = hv;
            }
        }
    }
}

// ---------------------------------------------------------------------------
// Kernel B: masked attention, 2x2 query tiling, fp16 storage, f32x2 math.
// One block (512 thr) per (b, head, 2x2 query patch). Thread owns 8 feats.
// Dynamic smem: red[16][4][16] | s_sc[16][4] | s_w[4][16] | ssa[4][64][65]
// Epilogue writes plain fp16 rows into g_sah [t][p][C].
// ---------------------------------------------------------------------------
__global__ __launch_bounds__(512, 2) void attn_kernel() {
    const int blk = blockIdx.x;            // 0..1023
    const int txq = blk & 7;
    const int tyq = (blk >> 3) & 7;
    const int n   = (blk >> 6) & 7;
    const int b_  = blk >> 9;
    const int tid = threadIdx.x;
    const int lane = tid & 31, wid = tid >> 5;

    extern __shared__ float smf[];
    float (*red)[4][16]  = (float (*)[4][16])smf;           // 1024 floats
    float (*s_sc)[4]     = (float (*)[4])(smf + 1024);      // 64
    float (*s_w)[16]     = (float (*)[16])(smf + 1088);     // 64
    float (*ssa)[64][65] = (float (*)[64][65])(smf + 1152); // 16640

    const int qy0 = tyq * 2, qx0 = txq * 2;
    const size_t slice = (size_t)(b_ * 8 + n) * SLICE;

    // q for 4 queries, 8 contiguous feats/thread as 4 packed f32x2 each
    u64 qp[4][4];
    #pragma unroll
    for (int qq = 0; qq < 4; qq++) {
        const int i = (qy0 + (qq >> 1)) * 16 + qx0 + (qq & 1);
        uint4 qv = *((const uint4*)(g_qh + slice + (size_t)i * FDIM) + tid);
        qp[qq][0] = h2tofx2(qv.x); qp[qq][1] = h2tofx2(qv.y);
        qp[qq][2] = h2tofx2(qv.z); qp[qq][3] = h2tofx2(qv.w);
    }

    const int j_safe = qy0 * 16 + qx0;

    // ---- scores: stream 16 k tiles of the 4x4 window ----
    #pragma unroll
    for (int e = 0; e < 16; e++) {
        const int ky = qy0 - 1 + (e >> 2), kx = qx0 - 1 + (e & 3);
        const bool inb = (ky >= 0) & (ky < 16) & (kx >= 0) & (kx < 16);
        const int j = inb ? (ky * 16 + kx) : j_safe;
        uint4 kv = *((const uint4*)(g_kh + slice + (size_t)j * FDIM) + tid);
        u64 kp[4];
        kp[0] = h2tofx2(kv.x); kp[1] = h2tofx2(kv.y);
        kp[2] = h2tofx2(kv.z); kp[3] = h2tofx2(kv.w);
        float d[4];
        #pragma unroll
        for (int qq = 0; qq < 4; qq++) {
            u64 d2 = 0ull;
            #pragma unroll
            for (int u = 0; u < 4; u++) d2 = ffma2(qp[qq][u], kp[u], d2);
            float lo, hi;
            unpack2(d2, lo, hi);
            d[qq] = lo + hi;
        }
        #pragma unroll
        for (int o = 16; o > 0; o >>= 1) {
            #pragma unroll
            for (int qq = 0; qq < 4; qq++) d[qq] += __shfl_down_sync(0xffffffffu, d[qq], o);
        }
        if (lane == 0) {
            #pragma unroll
            for (int qq = 0; qq < 4; qq++) red[e][qq][wid] = d[qq];
        }
    }
    __syncthreads();

    if (tid < 64) {
        const int e = tid >> 2, qq = tid & 3;
        float s = 0.f;
        #pragma unroll
        for (int w = 0; w < 16; w++) s += red[e][qq][w];
        s_sc[e][qq] = s * 0.015625f;   // 1/sqrt(4096)
    }
    __syncthreads();

    // ---- per-query masked softmax (threads 0..3) ----
    if (tid < 4) {
        const int qq = tid;
        const int qy = qy0 + (qq >> 1), qx = qx0 + (qq & 1);
        float sc[16];
        float m = -1e30f;
        #pragma unroll
        for (int e = 0; e < 16; e++) {
            const int ky = qy0 - 1 + (e >> 2), kx = qx0 - 1 + (e & 3);
            const bool valid = (ky >= 0) & (ky < 16) & (kx >= 0) & (kx < 16)
                             & (ky >= qy - 1) & (ky <= qy + 1)
                             & (kx >= qx - 1) & (kx <= qx + 1);
            sc[e] = valid ? s_sc[e][qq] : -1e30f;
            m = fmaxf(m, sc[e]);
        }
        float sum = 0.f;
        float w[16];
        #pragma unroll
        for (int e = 0; e < 16; e++) {
            w[e] = (sc[e] > -1e29f) ? __expf(sc[e] - m) : 0.f;
            sum += w[e];
        }
        const float inv = 1.0f / sum;
        #pragma unroll
        for (int e = 0; e < 16; e++) s_w[qq][e] = w[e] * inv;
    }
    __syncthreads();

    // ---- weighted V: stream 16 v tiles ----
    u64 fa[4][4];
    #pragma unroll
    for (int qq = 0; qq < 4; qq++)
        #pragma unroll
        for (int u = 0; u < 4; u++) fa[qq][u] = 0ull;

    #pragma unroll
    for (int e = 0; e < 16; e++) {
        const int ky = qy0 - 1 + (e >> 2), kx = qx0 - 1 + (e & 3);
        if ((ky < 0) | (ky >= 16) | (kx < 0) | (kx >= 16)) continue;
        const int j = ky * 16 + kx;
        uint4 vv = *((const uint4*)(g_vh + slice + (size_t)j * FDIM) + tid);
        u64 vp[4];
        vp[0] = h2tofx2(vv.x); vp[1] = h2tofx2(vv.y);
        vp[2] = h2tofx2(vv.z); vp[3] = h2tofx2(vv.w);
        #pragma unroll
        for (int qq = 0; qq < 4; qq++) {
            const float a = s_w[qq][e];
            const u64 a2 = pack2(a, a);
            #pragma unroll
            for (int u = 0; u < 4; u++) fa[qq][u] = ffma2(a2, vp[u], fa[qq][u]);
        }
    }

    // ---- epilogue: stage all 4 queries, one barrier, fp16 row stores ----
    const int ch = n & 1, sp = n >> 1, ys = sp >> 1, xs = sp & 1;
    const int sr0 = (tid & 7) * 8;         // staging row base (feature-major)
    const int scc = tid >> 3;              // staging cidx
    const int r   = tid >> 3;              // 0..63 local spatial (store)
    const int cb  = (tid & 7) * 8;         // 8-col chunk within the head's 64
    const int HWp = (ys * 8 + (r >> 3)) * 16 + xs * 8 + (r & 7);

    #pragma unroll
    for (int qq = 0; qq < 4; qq++) {
        #pragma unroll
        for (int u = 0; u < 4; u++) {
            float lo, hi;
            unpack2(fa[qq][u], lo, hi);
            ssa[qq][sr0 + 2 * u    ][scc] = lo;
            ssa[qq][sr0 + 2 * u + 1][scc] = hi;
        }
    }
    __syncthreads();

    #pragma unroll
    for (int qq = 0; qq < 4; qq++) {
        const int i = (qy0 + (qq >> 1)) * 16 + qx0 + (qq & 1);
        __half* rowp = g_sah + (size_t)(b_ * 256 + i) * 32768
                     + (size_t)HWp * 128 + ch * 64 + cb;
        __half2 h0 = __floats2half2_rn(ssa[qq][r][cb + 0], ssa[qq][r][cb + 1]);
        __half2 h1 = __floats2half2_rn(ssa[qq][r][cb + 2], ssa[qq][r][cb + 3]);
        __half2 h2 = __floats2half2_rn(ssa[qq][r][cb + 4], ssa[qq][r][cb + 5]);
        __half2 h3 = __floats2half2_rn(ssa[qq][r][cb + 6], ssa[qq][r][cb + 7]);
        uint4 v;
        v.x = *reinterpret_cast<uint32_t*>(&h0);
        v.y = *reinterpret_cast<uint32_t*>(&h1);
        v.z = *reinterpret_cast<uint32_t*>(&h2);
        v.w = *reinterpret_cast<uint32_t*>(&h3);
        *reinterpret_cast<uint4*>(rowp) = v;
    }
}

// ---------------------------------------------------------------------------
// Kernel C: output projection + bias (fp16 mma path)
// ---------------------------------------------------------------------------
__global__ __launch_bounds__(256, 2) void out_gemm(const float* __restrict__ b_out,
                                                   float* __restrict__ out) {
    const int t  = blockIdx.x;
    const int pt = blockIdx.y;

    extern __shared__ __align__(16) __half smem[];
    float acc[2][8][4];
    GemmCtx cx;
    gemm128_f16(g_wtoh,
                g_sah + (size_t)t * 32768 + pt * 16384,
                smem, acc, cx);

    #pragma unroll
    for (int mf = 0; mf < 2; mf++) {
        #pragma unroll
        for (int half_ = 0; half_ < 2; half_++) {
            const int d = cx.wm * 32 + mf * 16 + (cx.lane >> 2) + half_ * 8;
            const float bias = b_out[d];
            #pragma unroll
            for (int nf = 0; nf < 8; nf++) {
                const int c0 = cx.wn * 64 + nf * 8 + 2 * (cx.lane & 3);
                float2 v = make_float2(acc[mf][nf][half_ * 2] + bias,
                                       acc[mf][nf][half_ * 2 + 1] + bias);
                *reinterpret_cast<float2*>(out + (size_t)t * 32768
                                           + (size_t)d * 256 + pt * 128 + c0) = v;
            }
        }
    }
}

extern "C" void kernel_launch(void* const* d_in, const int* in_sizes, int n_in,
                              void* d_out, int out_size) {
    const float* seq   = (const float*)d_in[0];
    const float* w_qkv = (const float*)d_in[1];
    const float* w_out = (const float*)d_in[2];
    const float* b_out = (const float*)d_in[3];
    float* out = (float*)d_out;

    const int gemmsmem = 73728;
    const int attnsmem = 71168;
    cudaFuncSetAttribute(qkv_gemm, cudaFuncAttributeMaxDynamicSharedMemorySize, gemmsmem);
    cudaFuncSetAttribute(out_gemm, cudaFuncAttributeMaxDynamicSharedMemorySize, gemmsmem);
    cudaFuncSetAttribute(attn_kernel, cudaFuncAttributeMaxDynamicSharedMemorySize, attnsmem);

    prep_w<<<192, 256>>>(w_qkv, w_out);
    prep_x<<<512, 256>>>(seq);

    dim3 gA(3, NTOK, 2);
    qkv_gemm<<<gA, 256, gemmsmem>>>();

    attn_kernel<<<1024, 512, attnsmem>>>();

    dim3 gC(NTOK, 2);
    out_gemm<<<gC, 256, gemmsmem>>>(b_out, out);
}

// round 12
// speedup vs baseline: 2.5303x; 1.0874x over previous
#include <cuda_runtime.h>
#include <cuda_fp16.h>
#include <cstdint>

// Problem constants (fixed by dataset):
// b=2, s=256, C=128, H=W=16, YH=XH=CH=2 -> nH=8 heads, c=64, h=w=8, D=4096
// mask: 16x16 token grid, radius-1 neighborhood (<=9 keys per query)

#define NTOK   512
#define FDIM   4096
#define SLICE  (256*4096)
#define PITCH  72            // smem row pitch in halfs (64 data + 8 pad)

typedef unsigned long long u64;

// Scratch (device globals -- allocation-free per harness rules)
__device__ __align__(16) __half g_qh[2*8*256*4096];
__device__ __align__(16) __half g_kh[2*8*256*4096];
__device__ __align__(16) __half g_vh[2*8*256*4096];
__device__ __align__(16) __half g_sah[512*256*128];   // fp16 sa, [t][p][C]
__device__ __align__(16) __half g_xth[512*256*128];   // fp16 seq^T, [t][p][c]
__device__ __align__(16) __half g_wth[3*128*128];     // fp16 w_qkv [d][k]
__device__ __align__(16) __half g_wtoh[128*128];      // fp16 w_out [d][k]

// ---------------------------------------------------------------------------
// helpers
// ---------------------------------------------------------------------------
__device__ __forceinline__ void cp16h(__half* smem_dst, const __half* gsrc) {
    uint32_t s = (uint32_t)__cvta_generic_to_shared(smem_dst);
    asm volatile("cp.async.ca.shared.global [%0], [%1], 16;" :: "r"(s), "l"(gsrc));
}

__device__ __forceinline__ void ldsm4(uint32_t* r, const __half* p) {
    uint32_t a = (uint32_t)__cvta_generic_to_shared(p);
    asm volatile("ldmatrix.sync.aligned.m8n8.x4.shared.b16 {%0,%1,%2,%3}, [%4];"
                 : "=r"(r[0]), "=r"(r[1]), "=r"(r[2]), "=r"(r[3]) : "r"(a));
}

__device__ __forceinline__ void mma_f16(float* c, const uint32_t* a,
                                        uint32_t b0, uint32_t b1) {
    asm volatile(
        "mma.sync.aligned.m16n8k16.row.col.f32.f16.f16.f32 "
        "{%0,%1,%2,%3}, {%4,%5,%6,%7}, {%8,%9}, {%0,%1,%2,%3};"
        : "+f"(c[0]), "+f"(c[1]), "+f"(c[2]), "+f"(c[3])
        : "r"(a[0]), "r"(a[1]), "r"(a[2]), "r"(a[3]), "r"(b0), "r"(b1));
}

// ---- packed fp32 (B300 FFMA2 path) ----
__device__ __forceinline__ u64 pack2(float x, float y) {
    u64 r;
    asm("mov.b64 %0, {%1, %2};" : "=l"(r) : "f"(x), "f"(y));
    return r;
}
__device__ __forceinline__ void unpack2(u64 v, float& x, float& y) {
    asm("mov.b64 {%0, %1}, %2;" : "=f"(x), "=f"(y) : "l"(v));
}
__device__ __forceinline__ u64 ffma2(u64 a, u64 b, u64 c) {
    u64 d;
    asm("fma.rn.f32x2 %0, %1, %2, %3;" : "=l"(d) : "l"(a), "l"(b), "l"(c));
    return d;
}
__device__ __forceinline__ u64 h2tofx2(uint32_t h2bits) {
    float2 f = __half22float2(*reinterpret_cast<__half2*>(&h2bits));
    return pack2(f.x, f.y);
}

// ---------------------------------------------------------------------------
// prep_x: transpose seq[t][c][p] -> g_xth[t][p][c] fp16 (one block per token);
// first 192 blocks also convert the weights (prep_w folded in).
// ---------------------------------------------------------------------------
__global__ __launch_bounds__(256) void prep_x(const float* __restrict__ seq,
                                              const float* __restrict__ wq,
                                              const float* __restrict__ wo) {
    const int t = blockIdx.x;
    if (t < 192) {
        int i = t * 256 + threadIdx.x;   // 0..49151
        g_wth[i] = __float2half_rn(wq[i]);
        if (i < 16384) g_wtoh[i] = __float2half_rn(wo[i]);
    }

    __shared__ float tile[32][33];
    const float* src = seq + (size_t)t * 32768;
    __half* dst = g_xth + (size_t)t * 32768;

    for (int cc = 0; cc < 4; cc++)
        for (int pc = 0; pc < 8; pc++) {
            #pragma unroll
            for (int j = 0; j < 4; j++) {
                int id = threadIdx.x + j * 256;
                int r = id >> 5, cl = id & 31;
                tile[r][cl] = src[(cc * 32 + r) * 256 + pc * 32 + cl];
            }
            __syncthreads();
            #pragma unroll
            for (int j = 0; j < 4; j++) {
                int id = threadIdx.x + j * 256;
                int r = id >> 5, cl = id & 31;
                dst[(size_t)(pc * 32 + r) * 128 + cc * 32 + cl] = __float2half_rn(tile[cl][r]);
            }
            __syncthreads();
        }
}

// ---------------------------------------------------------------------------
// fp16 GEMM core: C[128,128] = W[128,128] * X^T (X rows [p][k], k contiguous).
// 8 warps (4x2), warp tile 32x64 = 2x8 m16n8k16. Two 64-K tiles prefetched via
// cp.async; ldmatrix.x4 fragment loads (conflict-free, pitch 72).
// smem: 2 stages x (A[128][72] + B[128][72]) halfs = 73728 B
// ---------------------------------------------------------------------------
struct GemmCtx { int lane, wm, wn; };

__device__ __forceinline__ void gemm128_f16(
    const __half* __restrict__ wmat,   // [128][128] fp16
    const __half* __restrict__ xmat,   // [128 p][128 k] fp16
    __half* smem, float acc[2][8][4], GemmCtx& cx)
{
    const int tid = threadIdx.x;
    const int lane = tid & 31, wid = tid >> 5;
    cx.lane = lane; cx.wm = wid >> 1; cx.wn = wid & 1;

    #pragma unroll
    for (int mf = 0; mf < 2; mf++)
        #pragma unroll
        for (int nf = 0; nf < 8; nf++)
            #pragma unroll
            for (int r = 0; r < 4; r++) acc[mf][nf][r] = 0.f;

    auto issue = [&](int buf, int kk) {
        __half* Ab = smem + buf * 18432;
        __half* Bb = Ab + 9216;
        #pragma unroll
        for (int i = 0; i < 4; i++) {
            int id  = tid + i * 256;        // 0..1023
            int row = id >> 3, seg = (id & 7) * 8;
            cp16h(Ab + row * PITCH + seg, wmat + row * 128 + kk + seg);
            cp16h(Bb + row * PITCH + seg, xmat + row * 128 + kk + seg);
        }
        asm volatile("cp.async.commit_group;" ::: "memory");
    };

    issue(0, 0);
    issue(1, 64);

    // per-lane ldmatrix address components
    const int l7 = lane & 7;
    const int aoff = (l7 + ((lane >> 3) & 1) * 8) * PITCH + ((lane >> 4) & 1) * 8;
    const int boff = (l7 + ((lane >> 4) & 1) * 8) * PITCH + ((lane >> 3) & 1) * 8;

    #pragma unroll
    for (int kt = 0; kt < 2; kt++) {
        if (kt == 0) {
            asm volatile("cp.async.wait_group 1;" ::: "memory");
        } else {
            asm volatile("cp.async.wait_group 0;" ::: "memory");
        }
        __syncthreads();

        const __half* A = smem + kt * 18432;
        const __half* B = A + 9216;

        #pragma unroll
        for (int k0 = 0; k0 < 64; k0 += 16) {
            uint32_t af[2][4], bf[4][4];
            #pragma unroll
            for (int mf = 0; mf < 2; mf++)
                ldsm4(af[mf], A + (cx.wm * 32 + mf * 16) * PITCH + k0 + aoff);
            #pragma unroll
            for (int np = 0; np < 4; np++)
                ldsm4(bf[np], B + (cx.wn * 64 + np * 16) * PITCH + k0 + boff);
            #pragma unroll
            for (int mf = 0; mf < 2; mf++)
                #pragma unroll
                for (int nf = 0; nf < 8; nf++)
                    mma_f16(acc[mf][nf], af[mf],
                            bf[nf >> 1][(nf & 1) * 2], bf[nf >> 1][(nf & 1) * 2 + 1]);
        }
    }
}

// ---------------------------------------------------------------------------
// Kernel A: QKV projection -> per-head fp16 layout.
// grid (3, 512, 2): x=dt so consecutive blocks reuse the same X tile via L2.
// Epilogue: a block's tile covers exactly 4 FULL head-feature-vectors
// (ys = pt fixed; 4 heads = xs,ch combos). Stage in smem (XOR-swizzled,
// conflict-free) then write 4 x 8KB contiguous rows with STG.128.
// ---------------------------------------------------------------------------
__global__ __launch_bounds__(256, 2) void qkv_gemm() {
    const int dt = blockIdx.x;
    const int t  = blockIdx.y;
    const int pt = blockIdx.z;
    const int tid = threadIdx.x;

    extern __shared__ __align__(16) __half smem[];
    float acc[2][8][4];
    GemmCtx cx;
    gemm128_f16(g_wth + dt * 16384,
                g_xth + (size_t)t * 32768 + pt * 16384,
                smem, acc, cx);

    // ---- staged epilogue ----
    __syncthreads();   // all warps done reading GEMM smem
    uint32_t* sst = reinterpret_cast<uint32_t*>(smem);   // [4 hidx][2048 words]
    const int lane = cx.lane;

    #pragma unroll
    for (int mf = 0; mf < 2; mf++) {
        #pragma unroll
        for (int h8 = 0; h8 < 2; h8++) {
            const int dl = cx.wm * 32 + mf * 16 + (lane >> 2) + h8 * 8;
            const int ch = dl >> 6, cidx = dl & 63;
            #pragma unroll
            for (int nf = 0; nf < 8; nf++) {
                const int xs = nf & 1;                 // Wi>>3
                const int hy = cx.wn * 4 + (nf >> 1);  // Hi&7
                const int hidx = xs * 2 + ch;
                __half2 hv = __floats2half2_rn(acc[mf][nf][h8 * 2],
                                               acc[mf][nf][h8 * 2 + 1]);
                // word layout: hidx*2048 + cidx*32 + swizzled-chunk*4 + wx/2
                const int word = hidx * 2048 + cidx * 32
                               + ((hy ^ (cidx & 7)) << 2) + (lane & 3);
                sst[word] = *reinterpret_cast<uint32_t*>(&hv);
            }
        }
    }
    __syncthreads();

    const int b_ = t >> 8, s_ = t & 255;
    __half* dst = (dt == 0) ? g_qh : (dt == 1) ? g_kh : g_vh;
    const uint4* sst4 = reinterpret_cast<const uint4*>(sst);

    // FULL coverage: 2048 chunks of 8 halfs = 4 heads x 4096 features
    #pragma unroll
    for (int i = 0; i < 8; i++) {
        const int idx = tid + i * 256;       // chunk id 0..2047
        const int hidx = idx >> 9, g = idx & 511;   // g = cidx*8 + hy, 0..511
        const int cidx = g >> 3, hy = g & 7;
        const int src = hidx * 512 + cidx * 8 + (hy ^ (cidx & 7));
        const int xs = hidx >> 1, ch = hidx & 1;
        const int n = (pt * 2 + xs) * 2 + ch;
        const size_t base = ((size_t)((b_ * 8 + n) * 256 + s_)) * FDIM + g * 8;
        *reinterpret_cast<uint4*>(dst + base) = sst4[src];
    }
}

// ---------------------------------------------------------------------------
// Kernel B: masked attention, 2x2 query tiling, fp16 storage, f32x2 math.
// One block (512 thr) per (b, head, 2x2 query patch). Thread owns 8 feats.
// Dynamic smem: red[16][4][16] | s_sc[16][4] | s_w[4][16] | ssa[4][64][65]
// ---------------------------------------------------------------------------
__global__ __launch_bounds__(512, 2) void attn_kernel() {
    const int blk = blockIdx.x;            // 0..1023
    const int txq = blk & 7;
    const int tyq = (blk >> 3) & 7;
    const int n   = (blk >> 6) & 7;
    const int b_  = blk >> 9;
    const int tid = threadIdx.x;
    const int lane = tid & 31, wid = tid >> 5;

    extern __shared__ float smf[];
    float (*red)[4][16]  = (float (*)[4][16])smf;           // 1024 floats
    float (*s_sc)[4]     = (float (*)[4])(smf + 1024);      // 64
    float (*s_w)[16]     = (float (*)[16])(smf + 1088);     // 64
    float (*ssa)[64][65] = (float (*)[64][65])(smf + 1152); // 16640

    const int qy0 = tyq * 2, qx0 = txq * 2;
    const size_t slice = (size_t)(b_ * 8 + n) * SLICE;

    // q for 4 queries, 8 contiguous feats/thread as 4 packed f32x2 each
    u64 qp[4][4];
    #pragma unroll
    for (int qq = 0; qq < 4; qq++) {
        const int i = (qy0 + (qq >> 1)) * 16 + qx0 + (qq & 1);
        uint4 qv = *((const uint4*)(g_qh + slice + (size_t)i * FDIM) + tid);
        qp[qq][0] = h2tofx2(qv.x); qp[qq][1] = h2tofx2(qv.y);
        qp[qq][2] = h2tofx2(qv.z); qp[qq][3] = h2tofx2(qv.w);
    }

    const int j_safe = qy0 * 16 + qx0;

    // ---- scores: stream 16 k tiles of the 4x4 window ----
    #pragma unroll
    for (int e = 0; e < 16; e++) {
        const int ky = qy0 - 1 + (e >> 2), kx = qx0 - 1 + (e & 3);
        const bool inb = (ky >= 0) & (ky < 16) & (kx >= 0) & (kx < 16);
        const int j = inb ? (ky * 16 + kx) : j_safe;
        uint4 kv = *((const uint4*)(g_kh + slice + (size_t)j * FDIM) + tid);
        u64 kp[4];
        kp[0] = h2tofx2(kv.x); kp[1] = h2tofx2(kv.y);
        kp[2] = h2tofx2(kv.z); kp[3] = h2tofx2(kv.w);
        float d[4];
        #pragma unroll
        for (int qq = 0; qq < 4; qq++) {
            u64 d2 = 0ull;
            #pragma unroll
            for (int u = 0; u < 4; u++) d2 = ffma2(qp[qq][u], kp[u], d2);
            float lo, hi;
            unpack2(d2, lo, hi);
            d[qq] = lo + hi;
        }
        #pragma unroll
        for (int o = 16; o > 0; o >>= 1) {
            #pragma unroll
            for (int qq = 0; qq < 4; qq++) d[qq] += __shfl_down_sync(0xffffffffu, d[qq], o);
        }
        if (lane == 0) {
            #pragma unroll
            for (int qq = 0; qq < 4; qq++) red[e][qq][wid] = d[qq];
        }
    }
    __syncthreads();

    if (tid < 64) {
        const int e = tid >> 2, qq = tid & 3;
        float s = 0.f;
        #pragma unroll
        for (int w = 0; w < 16; w++) s += red[e][qq][w];
        s_sc[e][qq] = s * 0.015625f;   // 1/sqrt(4096)
    }
    __syncthreads();

    // ---- per-query masked softmax (threads 0..3) ----
    if (tid < 4) {
        const int qq = tid;
        const int qy = qy0 + (qq >> 1), qx = qx0 + (qq & 1);
        float sc[16];
        float m = -1e30f;
        #pragma unroll
        for (int e = 0; e < 16; e++) {
            const int ky = qy0 - 1 + (e >> 2), kx = qx0 - 1 + (e & 3);
            const bool valid = (ky >= 0) & (ky < 16) & (kx >= 0) & (kx < 16)
                             & (ky >= qy - 1) & (ky <= qy + 1)
                             & (kx >= qx - 1) & (kx <= qx + 1);
            sc[e] = valid ? s_sc[e][qq] : -1e30f;
            m = fmaxf(m, sc[e]);
        }
        float sum = 0.f;
        float w[16];
        #pragma unroll
        for (int e = 0; e < 16; e++) {
            w[e] = (sc[e] > -1e29f) ? __expf(sc[e] - m) : 0.f;
            sum += w[e];
        }
        const float inv = 1.0f / sum;
        #pragma unroll
        for (int e = 0; e < 16; e++) s_w[qq][e] = w[e] * inv;
    }
    __syncthreads();

    // ---- weighted V: stream 16 v tiles ----
    u64 fa[4][4];
    #pragma unroll
    for (int qq = 0; qq < 4; qq++)
        #pragma unroll
        for (int u = 0; u < 4; u++) fa[qq][u] = 0ull;

    #pragma unroll
    for (int e = 0; e < 16; e++) {
        const int ky = qy0 - 1 + (e >> 2), kx = qx0 - 1 + (e & 3);
        if ((ky < 0) | (ky >= 16) | (kx < 0) | (kx >= 16)) continue;
        const int j = ky * 16 + kx;
        uint4 vv = *((const uint4*)(g_vh + slice + (size_t)j * FDIM) + tid);
        u64 vp[4];
        vp[0] = h2tofx2(vv.x); vp[1] = h2tofx2(vv.y);
        vp[2] = h2tofx2(vv.z); vp[3] = h2tofx2(vv.w);
        #pragma unroll
        for (int qq = 0; qq < 4; qq++) {
            const float a = s_w[qq][e];
            const u64 a2 = pack2(a, a);
            #pragma unroll
            for (int u = 0; u < 4; u++) fa[qq][u] = ffma2(a2, vp[u], fa[qq][u]);
        }
    }

    // ---- epilogue: stage all 4 queries, one barrier, fp16 row stores ----
    const int ch = n & 1, sp = n >> 1, ys = sp >> 1, xs = sp & 1;
    const int sr0 = (tid & 7) * 8;         // staging row base (feature-major)
    const int scc = tid >> 3;              // staging cidx
    const int r   = tid >> 3;              // 0..63 local spatial (store)
    const int cb  = (tid & 7) * 8;         // 8-col chunk within the head's 64
    const int HWp = (ys * 8 + (r >> 3)) * 16 + xs * 8 + (r & 7);

    #pragma unroll
    for (int qq = 0; qq < 4; qq++) {
        #pragma unroll
        for (int u = 0; u < 4; u++) {
            float lo, hi;
            unpack2(fa[qq][u], lo, hi);
            ssa[qq][sr0 + 2 * u    ][scc] = lo;
            ssa[qq][sr0 + 2 * u + 1][scc] = hi;
        }
    }
    __syncthreads();

    #pragma unroll
    for (int qq = 0; qq < 4; qq++) {
        const int i = (qy0 + (qq >> 1)) * 16 + qx0 + (qq & 1);
        __half* rowp = g_sah + (size_t)(b_ * 256 + i) * 32768
                     + (size_t)HWp * 128 + ch * 64 + cb;
        __half2 h0 = __floats2half2_rn(ssa[qq][r][cb + 0], ssa[qq][r][cb + 1]);
        __half2 h1 = __floats2half2_rn(ssa[qq][r][cb + 2], ssa[qq][r][cb + 3]);
        __half2 h2 = __floats2half2_rn(ssa[qq][r][cb + 4], ssa[qq][r][cb + 5]);
        __half2 h3 = __floats2half2_rn(ssa[qq][r][cb + 6], ssa[qq][r][cb + 7]);
        uint4 v;
        v.x = *reinterpret_cast<uint32_t*>(&h0);
        v.y = *reinterpret_cast<uint32_t*>(&h1);
        v.z = *reinterpret_cast<uint32_t*>(&h2);
        v.w = *reinterpret_cast<uint32_t*>(&h3);
        *reinterpret_cast<uint4*>(rowp) = v;
    }
}

// ---------------------------------------------------------------------------
// Kernel C: output projection + bias (fp16 mma path)
// ---------------------------------------------------------------------------
__global__ __launch_bounds__(256, 2) void out_gemm(const float* __restrict__ b_out,
                                                   float* __restrict__ out) {
    const int t  = blockIdx.x;
    const int pt = blockIdx.y;

    extern __shared__ __align__(16) __half smem[];
    float acc[2][8][4];
    GemmCtx cx;
    gemm128_f16(g_wtoh,
                g_sah + (size_t)t * 32768 + pt * 16384,
                smem, acc, cx);

    #pragma unroll
    for (int mf = 0; mf < 2; mf++) {
        #pragma unroll
        for (int half_ = 0; half_ < 2; half_++) {
            const int d = cx.wm * 32 + mf * 16 + (cx.lane >> 2) + half_ * 8;
            const float bias = b_out[d];
            #pragma unroll
            for (int nf = 0; nf < 8; nf++) {
                const int c0 = cx.wn * 64 + nf * 8 + 2 * (cx.lane & 3);
                float2 v = make_float2(acc[mf][nf][half_ * 2] + bias,
                                       acc[mf][nf][half_ * 2 + 1] + bias);
                *reinterpret_cast<float2*>(out + (size_t)t * 32768
                                           + (size_t)d * 256 + pt * 128 + c0) = v;
            }
        }
    }
}

extern "C" void kernel_launch(void* const* d_in, const int* in_sizes, int n_in,
                              void* d_out, int out_size) {
    const float* seq   = (const float*)d_in[0];
    const float* w_qkv = (const float*)d_in[1];
    const float* w_out = (const float*)d_in[2];
    const float* b_out = (const float*)d_in[3];
    float* out = (float*)d_out;

    const int gemmsmem = 73728;
    const int attnsmem = 71168;
    cudaFuncSetAttribute(qkv_gemm, cudaFuncAttributeMaxDynamicSharedMemorySize, gemmsmem);
    cudaFuncSetAttribute(out_gemm, cudaFuncAttributeMaxDynamicSharedMemorySize, gemmsmem);
    cudaFuncSetAttribute(attn_kernel, cudaFuncAttributeMaxDynamicSharedMemorySize, attnsmem);

    prep_x<<<512, 256>>>(seq, w_qkv, w_out);

    dim3 gA(3, NTOK, 2);
    qkv_gemm<<<gA, 256, gemmsmem>>>();

    attn_kernel<<<1024, 512, attnsmem>>>();

    dim3 gC(NTOK, 2);
    out_gemm<<<gC, 256, gemmsmem>>>(b_out, out);
}

// round 13
// speedup vs baseline: 2.5411x; 1.0042x over previous
#include <cuda_runtime.h>
#include <cuda_fp16.h>
#include <cstdint>

// Problem constants (fixed by dataset):
// b=2, s=256, C=128, H=W=16, YH=XH=CH=2 -> nH=8 heads, c=64, h=w=8, D=4096
// mask: 16x16 token grid, radius-1 neighborhood (<=9 keys per query)

#define NTOK   512
#define FDIM   4096
#define SLICE  (256*4096)
#define PITCH  72            // smem row pitch in halfs (64 data + 8 pad)

typedef unsigned long long u64;

// Scratch (device globals -- allocation-free per harness rules)
__device__ __align__(16) __half g_qh[2*8*256*4096];
__device__ __align__(16) __half g_kh[2*8*256*4096];
__device__ __align__(16) __half g_vh[2*8*256*4096];
__device__ __align__(16) __half g_sah[512*256*128];   // fp16 sa, [t][p][C]
__device__ __align__(16) __half g_xth[512*256*128];   // fp16 seq^T, [t][p][c]
__device__ __align__(16) __half g_wth[3*128*128];     // fp16 w_qkv [d][k]
__device__ __align__(16) __half g_wtoh[128*128];      // fp16 w_out [d][k]

// ---------------------------------------------------------------------------
// helpers
// ---------------------------------------------------------------------------
__device__ __forceinline__ void cp16h(__half* smem_dst, const __half* gsrc) {
    uint32_t s = (uint32_t)__cvta_generic_to_shared(smem_dst);
    asm volatile("cp.async.ca.shared.global [%0], [%1], 16;" :: "r"(s), "l"(gsrc));
}

__device__ __forceinline__ void ldsm4(uint32_t* r, const __half* p) {
    uint32_t a = (uint32_t)__cvta_generic_to_shared(p);
    asm volatile("ldmatrix.sync.aligned.m8n8.x4.shared.b16 {%0,%1,%2,%3}, [%4];"
                 : "=r"(r[0]), "=r"(r[1]), "=r"(r[2]), "=r"(r[3]) : "r"(a));
}

__device__ __forceinline__ void mma_f16(float* c, const uint32_t* a,
                                        uint32_t b0, uint32_t b1) {
    asm volatile(
        "mma.sync.aligned.m16n8k16.row.col.f32.f16.f16.f32 "
        "{%0,%1,%2,%3}, {%4,%5,%6,%7}, {%8,%9}, {%0,%1,%2,%3};"
        : "+f"(c[0]), "+f"(c[1]), "+f"(c[2]), "+f"(c[3])
        : "r"(a[0]), "r"(a[1]), "r"(a[2]), "r"(a[3]), "r"(b0), "r"(b1));
}

// ---- packed fp32 (B300 FFMA2 path) ----
__device__ __forceinline__ u64 pack2(float x, float y) {
    u64 r;
    asm("mov.b64 %0, {%1, %2};" : "=l"(r) : "f"(x), "f"(y));
    return r;
}
__device__ __forceinline__ void unpack2(u64 v, float& x, float& y) {
    asm("mov.b64 {%0, %1}, %2;" : "=f"(x), "=f"(y) : "l"(v));
}
__device__ __forceinline__ u64 ffma2(u64 a, u64 b, u64 c) {
    u64 d;
    asm("fma.rn.f32x2 %0, %1, %2, %3;" : "=l"(d) : "l"(a), "l"(b), "l"(c));
    return d;
}
__device__ __forceinline__ u64 h2tofx2(uint32_t h2bits) {
    float2 f = __half22float2(*reinterpret_cast<__half2*>(&h2bits));
    return pack2(f.x, f.y);
}

// ---------------------------------------------------------------------------
// prep_x: transpose seq[t][c][p] -> g_xth[t][p][c] fp16, 2 passes through a
// [128 c][129 p] float tile (3 barriers total). First 192 blocks also
// convert the weights.
// ---------------------------------------------------------------------------
__global__ __launch_bounds__(256) void prep_x(const float* __restrict__ seq,
                                              const float* __restrict__ wq,
                                              const float* __restrict__ wo) {
    const int t = blockIdx.x;
    const int tid = threadIdx.x;
    if (t < 192) {
        int i = t * 256 + tid;   // 0..49151
        g_wth[i] = __float2half_rn(wq[i]);
        if (i < 16384) g_wtoh[i] = __float2half_rn(wo[i]);
    }

    extern __shared__ float tl[];   // [128 c][129 p_local]
    const float* src = seq + (size_t)t * 32768;
    __half* dst = g_xth + (size_t)t * 32768;

    #pragma unroll 1
    for (int pass = 0; pass < 2; pass++) {
        if (pass) __syncthreads();
        // load: tl[c][p_local] = src[c][pass*128 + p_local]
        #pragma unroll
        for (int j = 0; j < 16; j++) {
            int idx = tid + j * 256;            // 0..4095
            int c = idx >> 5, p4 = (idx & 31) * 4;
            float4 v = *reinterpret_cast<const float4*>(src + c * 256 + pass * 128 + p4);
            float* row = tl + c * 129 + p4;
            row[0] = v.x; row[1] = v.y; row[2] = v.z; row[3] = v.w;
        }
        __syncthreads();
        // store transposed: dst[(pass*128+pl)*128 + c] = tl[c][pl]
        #pragma unroll
        for (int j = 0; j < 8; j++) {
            int idx = tid + j * 256;            // 0..2047
            int pl = idx >> 4;
            int m = idx & 15;
            int c0 = ((m + pl) & 15) * 8;       // rotate chunks to spread banks
            __half2 h[4];
            #pragma unroll
            for (int u = 0; u < 4; u++)
                h[u] = __floats2half2_rn(tl[(c0 + 2 * u) * 129 + pl],
                                         tl[(c0 + 2 * u + 1) * 129 + pl]);
            uint4 v;
            v.x = *reinterpret_cast<uint32_t*>(&h[0]);
            v.y = *reinterpret_cast<uint32_t*>(&h[1]);
            v.z = *reinterpret_cast<uint32_t*>(&h[2]);
            v.w = *reinterpret_cast<uint32_t*>(&h[3]);
            *reinterpret_cast<uint4*>(dst + (size_t)(pass * 128 + pl) * 128 + c0) = v;
        }
    }
}

// ---------------------------------------------------------------------------
// Kernel A: QKV projection, dt-merged. grid (512, 2) = (t, pt); one block
// computes q,k,v for its (t,pt) tile with the X tile RESIDENT in smem.
// smem: X[2 kt][128][72] | W[2 kt][128][72] (single dt buffer) | staging 32KB.
// W chunk1 load hides behind chunk0's MMAs; W(dt+1) issued during dt epilogue.
// ---------------------------------------------------------------------------
__global__ __launch_bounds__(256, 2) void qkv_gemm() {
    const int t  = blockIdx.x;
    const int pt = blockIdx.y;
    const int tid = threadIdx.x;
    const int lane = tid & 31, wid = tid >> 5;
    const int wm = wid >> 1, wn = wid & 1;

    extern __shared__ __align__(16) __half smem[];
    __half* Xb   = smem;                 // [2][128][72] halfs
    __half* Wbuf = smem + 18432;         // [2][128][72] halfs
    uint32_t* sst = reinterpret_cast<uint32_t*>(smem + 36864);   // 8192 words

    const __half* xmat = g_xth + (size_t)t * 32768 + pt * 16384;

    // G0: X, both 64-k chunks
    #pragma unroll
    for (int kt = 0; kt < 2; kt++)
        #pragma unroll
        for (int i = 0; i < 4; i++) {
            int id = tid + i * 256;
            int row = id >> 3, seg = (id & 7) * 8;
            cp16h(Xb + kt * 9216 + row * PITCH + seg, xmat + row * 128 + kt * 64 + seg);
        }
    asm volatile("cp.async.commit_group;" ::: "memory");

    auto issueW = [&](int dt) {
        const __half* wsrc = g_wth + dt * 16384;
        #pragma unroll
        for (int kt = 0; kt < 2; kt++) {
            #pragma unroll
            for (int i = 0; i < 4; i++) {
                int id = tid + i * 256;
                int row = id >> 3, seg = (id & 7) * 8;
                cp16h(Wbuf + kt * 9216 + row * PITCH + seg, wsrc + row * 128 + kt * 64 + seg);
            }
            asm volatile("cp.async.commit_group;" ::: "memory");
        }
    };
    issueW(0);   // G1 = chunk0, G2 = chunk1

    const int l7 = lane & 7;
    const int aoff = (l7 + ((lane >> 3) & 1) * 8) * PITCH + ((lane >> 4) & 1) * 8;
    const int boff = (l7 + ((lane >> 4) & 1) * 8) * PITCH + ((lane >> 3) & 1) * 8;

    const int b_ = t >> 8, s_ = t & 255;

    #pragma unroll 1
    for (int dt = 0; dt < 3; dt++) {
        float acc[2][8][4];
        #pragma unroll
        for (int mf = 0; mf < 2; mf++)
            #pragma unroll
            for (int nf = 0; nf < 8; nf++)
                #pragma unroll
                for (int r = 0; r < 4; r++) acc[mf][nf][r] = 0.f;

        #pragma unroll
        for (int kt = 0; kt < 2; kt++) {
            if (kt == 0) asm volatile("cp.async.wait_group 1;" ::: "memory");
            else         asm volatile("cp.async.wait_group 0;" ::: "memory");
            __syncthreads();

            const __half* A = Wbuf + kt * 9216;
            const __half* B = Xb   + kt * 9216;

            #pragma unroll
            for (int k0 = 0; k0 < 64; k0 += 16) {
                uint32_t af[2][4], bf[4][4];
                #pragma unroll
                for (int mf = 0; mf < 2; mf++)
                    ldsm4(af[mf], A + (wm * 32 + mf * 16) * PITCH + k0 + aoff);
                #pragma unroll
                for (int np = 0; np < 4; np++)
                    ldsm4(bf[np], B + (wn * 64 + np * 16) * PITCH + k0 + boff);
                #pragma unroll
                for (int mf = 0; mf < 2; mf++)
                    #pragma unroll
                    for (int nf = 0; nf < 8; nf++)
                        mma_f16(acc[mf][nf], af[mf],
                                bf[nf >> 1][(nf & 1) * 2], bf[nf >> 1][(nf & 1) * 2 + 1]);
            }
        }
        __syncthreads();             // W buffer + staging fully free

        if (dt < 2) issueW(dt + 1);  // overlap next W load with epilogue

        // ---- staged epilogue (writer: R12-proven mapping) ----
        #pragma unroll
        for (int mf = 0; mf < 2; mf++) {
            #pragma unroll
            for (int h8 = 0; h8 < 2; h8++) {
                const int dl = wm * 32 + mf * 16 + (lane >> 2) + h8 * 8;
                const int ch = dl >> 6, cidx = dl & 63;
                #pragma unroll
                for (int nf = 0; nf < 8; nf++) {
                    const int xs = nf & 1;
                    const int hy = wn * 4 + (nf >> 1);
                    const int hidx = xs * 2 + ch;
                    __half2 hv = __floats2half2_rn(acc[mf][nf][h8 * 2],
                                                   acc[mf][nf][h8 * 2 + 1]);
                    const int word = hidx * 2048 + cidx * 32
                                   + ((hy ^ (cidx & 7)) << 2) + (lane & 3);
                    sst[word] = *reinterpret_cast<uint32_t*>(&hv);
                }
            }
        }
        __syncthreads();

        __half* dst = (dt == 0) ? g_qh : (dt == 1) ? g_kh : g_vh;
        const uint4* sst4 = reinterpret_cast<const uint4*>(sst);
        #pragma unroll
        for (int i = 0; i < 8; i++) {
            const int idx = tid + i * 256;               // chunk id 0..2047
            const int hidx = idx >> 9, g = idx & 511;
            const int cidx = g >> 3, hy = g & 7;
            const int src = hidx * 512 + cidx * 8 + (hy ^ (cidx & 7));
            const int xs = hidx >> 1, ch = hidx & 1;
            const int n = (pt * 2 + xs) * 2 + ch;
            const size_t base = ((size_t)((b_ * 8 + n) * 256 + s_)) * FDIM + g * 8;
            *reinterpret_cast<uint4*>(dst + base) = sst4[src];
        }
        // next iteration's kt0 __syncthreads orders staging reuse after stores
    }
}

// ---------------------------------------------------------------------------
// fp16 GEMM core for out_gemm (unchanged, proven)
// ---------------------------------------------------------------------------
struct GemmCtx { int lane, wm, wn; };

__device__ __forceinline__ void gemm128_f16(
    const __half* __restrict__ wmat,
    const __half* __restrict__ xmat,
    __half* smem, float acc[2][8][4], GemmCtx& cx)
{
    const int tid = threadIdx.x;
    const int lane = tid & 31, wid = tid >> 5;
    cx.lane = lane; cx.wm = wid >> 1; cx.wn = wid & 1;

    #pragma unroll
    for (int mf = 0; mf < 2; mf++)
        #pragma unroll
        for (int nf = 0; nf < 8; nf++)
            #pragma unroll
            for (int r = 0; r < 4; r++) acc[mf][nf][r] = 0.f;

    auto issue = [&](int buf, int kk) {
        __half* Ab = smem + buf * 18432;
        __half* Bb = Ab + 9216;
        #pragma unroll
        for (int i = 0; i < 4; i++) {
            int id  = tid + i * 256;
            int row = id >> 3, seg = (id & 7) * 8;
            cp16h(Ab + row * PITCH + seg, wmat + row * 128 + kk + seg);
            cp16h(Bb + row * PITCH + seg, xmat + row * 128 + kk + seg);
        }
        asm volatile("cp.async.commit_group;" ::: "memory");
    };

    issue(0, 0);
    issue(1, 64);

    const int l7 = lane & 7;
    const int aoff = (l7 + ((lane >> 3) & 1) * 8) * PITCH + ((lane >> 4) & 1) * 8;
    const int boff = (l7 + ((lane >> 4) & 1) * 8) * PITCH + ((lane >> 3) & 1) * 8;

    #pragma unroll
    for (int kt = 0; kt < 2; kt++) {
        if (kt == 0) asm volatile("cp.async.wait_group 1;" ::: "memory");
        else         asm volatile("cp.async.wait_group 0;" ::: "memory");
        __syncthreads();

        const __half* A = smem + kt * 18432;
        const __half* B = A + 9216;

        #pragma unroll
        for (int k0 = 0; k0 < 64; k0 += 16) {
            uint32_t af[2][4], bf[4][4];
            #pragma unroll
            for (int mf = 0; mf < 2; mf++)
                ldsm4(af[mf], A + (cx.wm * 32 + mf * 16) * PITCH + k0 + aoff);
            #pragma unroll
            for (int np = 0; np < 4; np++)
                ldsm4(bf[np], B + (cx.wn * 64 + np * 16) * PITCH + k0 + boff);
            #pragma unroll
            for (int mf = 0; mf < 2; mf++)
                #pragma unroll
                for (int nf = 0; nf < 8; nf++)
                    mma_f16(acc[mf][nf], af[mf],
                            bf[nf >> 1][(nf & 1) * 2], bf[nf >> 1][(nf & 1) * 2 + 1]);
        }
    }
}

// ---------------------------------------------------------------------------
// Kernel B: masked attention (unchanged from R12 pass)
// ---------------------------------------------------------------------------
__global__ __launch_bounds__(512, 2) void attn_kernel() {
    const int blk = blockIdx.x;
    const int txq = blk & 7;
    const int tyq = (blk >> 3) & 7;
    const int n   = (blk >> 6) & 7;
    const int b_  = blk >> 9;
    const int tid = threadIdx.x;
    const int lane = tid & 31, wid = tid >> 5;

    extern __shared__ float smf[];
    float (*red)[4][16]  = (float (*)[4][16])smf;
    float (*s_sc)[4]     = (float (*)[4])(smf + 1024);
    float (*s_w)[16]     = (float (*)[16])(smf + 1088);
    float (*ssa)[64][65] = (float (*)[64][65])(smf + 1152);

    const int qy0 = tyq * 2, qx0 = txq * 2;
    const size_t slice = (size_t)(b_ * 8 + n) * SLICE;

    u64 qp[4][4];
    #pragma unroll
    for (int qq = 0; qq < 4; qq++) {
        const int i = (qy0 + (qq >> 1)) * 16 + qx0 + (qq & 1);
        uint4 qv = *((const uint4*)(g_qh + slice + (size_t)i * FDIM) + tid);
        qp[qq][0] = h2tofx2(qv.x); qp[qq][1] = h2tofx2(qv.y);
        qp[qq][2] = h2tofx2(qv.z); qp[qq][3] = h2tofx2(qv.w);
    }

    const int j_safe = qy0 * 16 + qx0;

    #pragma unroll
    for (int e = 0; e < 16; e++) {
        const int ky = qy0 - 1 + (e >> 2), kx = qx0 - 1 + (e & 3);
        const bool inb = (ky >= 0) & (ky < 16) & (kx >= 0) & (kx < 16);
        const int j = inb ? (ky * 16 + kx) : j_safe;
        uint4 kv = *((const uint4*)(g_kh + slice + (size_t)j * FDIM) + tid);
        u64 kp[4];
        kp[0] = h2tofx2(kv.x); kp[1] = h2tofx2(kv.y);
        kp[2] = h2tofx2(kv.z); kp[3] = h2tofx2(kv.w);
        float d[4];
        #pragma unroll
        for (int qq = 0; qq < 4; qq++) {
            u64 d2 = 0ull;
            #pragma unroll
            for (int u = 0; u < 4; u++) d2 = ffma2(qp[qq][u], kp[u], d2);
            float lo, hi;
            unpack2(d2, lo, hi);
            d[qq] = lo + hi;
        }
        #pragma unroll
        for (int o = 16; o > 0; o >>= 1) {
            #pragma unroll
            for (int qq = 0; qq < 4; qq++) d[qq] += __shfl_down_sync(0xffffffffu, d[qq], o);
        }
        if (lane == 0) {
            #pragma unroll
            for (int qq = 0; qq < 4; qq++) red[e][qq][wid] = d[qq];
        }
    }
    __syncthreads();

    if (tid < 64) {
        const int e = tid >> 2, qq = tid & 3;
        float s = 0.f;
        #pragma unroll
        for (int w = 0; w < 16; w++) s += red[e][qq][w];
        s_sc[e][qq] = s * 0.015625f;
    }
    __syncthreads();

    if (tid < 4) {
        const int qq = tid;
        const int qy = qy0 + (qq >> 1), qx = qx0 + (qq & 1);
        float sc[16];
        float m = -1e30f;
        #pragma unroll
        for (int e = 0; e < 16; e++) {
            const int ky = qy0 - 1 + (e >> 2), kx = qx0 - 1 + (e & 3);
            const bool valid = (ky >= 0) & (ky < 16) & (kx >= 0) & (kx < 16)
                             & (ky >= qy - 1) & (ky <= qy + 1)
                             & (kx >= qx - 1) & (kx <= qx + 1);
            sc[e] = valid ? s_sc[e][qq] : -1e30f;
            m = fmaxf(m, sc[e]);
        }
        float sum = 0.f;
        float w[16];
        #pragma unroll
        for (int e = 0; e < 16; e++) {
            w[e] = (sc[e] > -1e29f) ? __expf(sc[e] - m) : 0.f;
            sum += w[e];
        }
        const float inv = 1.0f / sum;
        #pragma unroll
        for (int e = 0; e < 16; e++) s_w[qq][e] = w[e] * inv;
    }
    __syncthreads();

    u64 fa[4][4];
    #pragma unroll
    for (int qq = 0; qq < 4; qq++)
        #pragma unroll
        for (int u = 0; u < 4; u++) fa[qq][u] = 0ull;

    #pragma unroll
    for (int e = 0; e < 16; e++) {
        const int ky = qy0 - 1 + (e >> 2), kx = qx0 - 1 + (e & 3);
        if ((ky < 0) | (ky >= 16) | (kx < 0) | (kx >= 16)) continue;
        const int j = ky * 16 + kx;
        uint4 vv = *((const uint4*)(g_vh + slice + (size_t)j * FDIM) + tid);
        u64 vp[4];
        vp[0] = h2tofx2(vv.x); vp[1] = h2tofx2(vv.y);
        vp[2] = h2tofx2(vv.z); vp[3] = h2tofx2(vv.w);
        #pragma unroll
        for (int qq = 0; qq < 4; qq++) {
            const float a = s_w[qq][e];
            const u64 a2 = pack2(a, a);
            #pragma unroll
            for (int u = 0; u < 4; u++) fa[qq][u] = ffma2(a2, vp[u], fa[qq][u]);
        }
    }

    const int ch = n & 1, sp = n >> 1, ys = sp >> 1, xs = sp & 1;
    const int sr0 = (tid & 7) * 8;
    const int scc = tid >> 3;
    const int r   = tid >> 3;
    const int cb  = (tid & 7) * 8;
    const int HWp = (ys * 8 + (r >> 3)) * 16 + xs * 8 + (r & 7);

    #pragma unroll
    for (int qq = 0; qq < 4; qq++) {
        #pragma unroll
        for (int u = 0; u < 4; u++) {
            float lo, hi;
            unpack2(fa[qq][u], lo, hi);
            ssa[qq][sr0 + 2 * u    ][scc] = lo;
            ssa[qq][sr0 + 2 * u + 1][scc] = hi;
        }
    }
    __syncthreads();

    #pragma unroll
    for (int qq = 0; qq < 4; qq++) {
        const int i = (qy0 + (qq >> 1)) * 16 + qx0 + (qq & 1);
        __half* rowp = g_sah + (size_t)(b_ * 256 + i) * 32768
                     + (size_t)HWp * 128 + ch * 64 + cb;
        __half2 h0 = __floats2half2_rn(ssa[qq][r][cb + 0], ssa[qq][r][cb + 1]);
        __half2 h1 = __floats2half2_rn(ssa[qq][r][cb + 2], ssa[qq][r][cb + 3]);
        __half2 h2 = __floats2half2_rn(ssa[qq][r][cb + 4], ssa[qq][r][cb + 5]);
        __half2 h3 = __floats2half2_rn(ssa[qq][r][cb + 6], ssa[qq][r][cb + 7]);
        uint4 v;
        v.x = *reinterpret_cast<uint32_t*>(&h0);
        v.y = *reinterpret_cast<uint32_t*>(&h1);
        v.z = *reinterpret_cast<uint32_t*>(&h2);
        v.w = *reinterpret_cast<uint32_t*>(&h3);
        *reinterpret_cast<uint4*>(rowp) = v;
    }
}

// ---------------------------------------------------------------------------
// Kernel C: output projection + bias (unchanged)
// ---------------------------------------------------------------------------
__global__ __launch_bounds__(256, 2) void out_gemm(const float* __restrict__ b_out,
                                                   float* __restrict__ out) {
    const int t  = blockIdx.x;
    const int pt = blockIdx.y;

    extern __shared__ __align__(16) __half smem[];
    float acc[2][8][4];
    GemmCtx cx;
    gemm128_f16(g_wtoh,
                g_sah + (size_t)t * 32768 + pt * 16384,
                smem, acc, cx);

    #pragma unroll
    for (int mf = 0; mf < 2; mf++) {
        #pragma unroll
        for (int half_ = 0; half_ < 2; half_++) {
            const int d = cx.wm * 32 + mf * 16 + (cx.lane >> 2) + half_ * 8;
            const float bias = b_out[d];
            #pragma unroll
            for (int nf = 0; nf < 8; nf++) {
                const int c0 = cx.wn * 64 + nf * 8 + 2 * (cx.lane & 3);
                float2 v = make_float2(acc[mf][nf][half_ * 2] + bias,
                                       acc[mf][nf][half_ * 2 + 1] + bias);
                *reinterpret_cast<float2*>(out + (size_t)t * 32768
                                           + (size_t)d * 256 + pt * 128 + c0) = v;
            }
        }
    }
}

extern "C" void kernel_launch(void* const* d_in, const int* in_sizes, int n_in,
                              void* d_out, int out_size) {
    const float* seq   = (const float*)d_in[0];
    const float* w_qkv = (const float*)d_in[1];
    const float* w_out = (const float*)d_in[2];
    const float* b_out = (const float*)d_in[3];
    float* out = (float*)d_out;

    const int prepsmem = 66048;     // 128*129*4
    const int qkvsmem  = 106496;    // X 36864B + W 36864B + staging 32768B
    const int gemmsmem = 73728;
    const int attnsmem = 71168;
    cudaFuncSetAttribute(prep_x,   cudaFuncAttributeMaxDynamicSharedMemorySize, prepsmem);
    cudaFuncSetAttribute(qkv_gemm, cudaFuncAttributeMaxDynamicSharedMemorySize, qkvsmem);
    cudaFuncSetAttribute(out_gemm, cudaFuncAttributeMaxDynamicSharedMemorySize, gemmsmem);
    cudaFuncSetAttribute(attn_kernel, cudaFuncAttributeMaxDynamicSharedMemorySize, attnsmem);

    prep_x<<<512, 256, prepsmem>>>(seq, w_qkv, w_out);

    dim3 gA(NTOK, 2);
    qkv_gemm<<<gA, 256, qkvsmem>>>();

    attn_kernel<<<1024, 512, attnsmem>>>();

    dim3 gC(NTOK, 2);
    out_gemm<<<gC, 256, gemmsmem>>>(b_out, out);
}